// round 1
// baseline (speedup 1.0000x reference)
#include <cuda_runtime.h>
#include <cuda_bf16.h>

// Problem constants (fixed by the dataset)
#define MAX_N 100000
#define MAX_E 1600000
#define D 64          // feature dim (all layers)
#define CAT_STRIDE 192  // 3 * D, xs_cat row stride

// Scratch (device globals — no allocation allowed)
__device__ float g_agg[MAX_N * D];      // per-layer aggregation buffer (25.6 MB)
__device__ float g_inv_out[MAX_N];      // out-degree^{-1/2} (src-side norm)
__device__ float g_inv_in[MAX_N];       // in-degree^{-1/2}  (dst-side norm)

// ---------------------------------------------------------------------------
// Zero a float buffer with float4 stores
__global__ void zero_f4_kernel(float4* __restrict__ p, int n4) {
    int i = blockIdx.x * blockDim.x + threadIdx.x;
    if (i < n4) p[i] = make_float4(0.f, 0.f, 0.f, 0.f);
}

// Zero both degree accumulators
__global__ void zero_deg_kernel(float* __restrict__ a, float* __restrict__ b, int n) {
    int i = blockIdx.x * blockDim.x + threadIdx.x;
    if (i < n) { a[i] = 0.f; b[i] = 0.f; }
}

// Count degrees via float atomics (counts are exact in fp32 up to 2^24)
__global__ void deg_count_kernel(const int* __restrict__ src, const int* __restrict__ dst,
                                 float* __restrict__ dout, float* __restrict__ din, int e) {
    int i = blockIdx.x * blockDim.x + threadIdx.x;
    if (i < e) {
        atomicAdd(&dout[src[i]], 1.0f);
        atomicAdd(&din[dst[i]], 1.0f);
    }
}

// inv = rsqrt(clamp(deg, 1))  (in place)
__global__ void make_inv_kernel(float* __restrict__ a, float* __restrict__ b, int n) {
    int i = blockIdx.x * blockDim.x + threadIdx.x;
    if (i < n) {
        a[i] = rsqrtf(fmaxf(a[i], 1.0f));
        b[i] = rsqrtf(fmaxf(b[i], 1.0f));
    }
}

// ---------------------------------------------------------------------------
// Scatter: agg[dst] += x[src] * inv_out[src]
// 16 lanes per edge, float4 per lane -> 256B coalesced gather, vector REDG add.
__global__ void scatter_kernel(const float* __restrict__ x, int xstride,
                               const int* __restrict__ src, const int* __restrict__ dst,
                               const float* __restrict__ inv_out,
                               float* __restrict__ agg, int e) {
    int idx = blockIdx.x * blockDim.x + threadIdx.x;
    int edge = idx >> 4;
    if (edge >= e) return;
    int c = (idx & 15) << 2;

    int s = __ldg(&src[edge]);
    int d = __ldg(&dst[edge]);
    float sc = __ldg(&inv_out[s]);

    const float4 v4 = *reinterpret_cast<const float4*>(x + (long)s * xstride + c);
    float vx = v4.x * sc, vy = v4.y * sc, vz = v4.z * sc, vw = v4.w * sc;

    float* a = agg + (long)d * D + c;
    asm volatile("red.global.add.v4.f32 [%0], {%1, %2, %3, %4};"
                 :: "l"(a), "f"(vx), "f"(vy), "f"(vz), "f"(vw) : "memory");
}

// ---------------------------------------------------------------------------
// Dense: y = relu((agg[n] * inv_in[n]) @ W + b)
//   - writes y into xs_cat region (stride 192) at the layer's 64-col block
//   - writes row-sum(y) into x_pool segment
// One node per warp. W staged in shared as float2[64][32] (k-major),
// x-row held in registers (float2/lane) and broadcast via shfl.
__global__ void dense_kernel(const float* __restrict__ agg,
                             const float* __restrict__ inv_in,
                             const float* __restrict__ W, const float* __restrict__ b,
                             float* __restrict__ cat_out,   // base + 3N + l*64
                             float* __restrict__ pool_out,  // base + l*N
                             int n) {
    __shared__ float2 Ws[D][32];   // Ws[k][j] = (W[k][2j], W[k][2j+1])
    __shared__ float  bs[D];

    int tid = threadIdx.x;
    const float2* Wf2 = reinterpret_cast<const float2*>(W);
    for (int i = tid; i < D * 32; i += blockDim.x)
        Ws[i >> 5][i & 31] = Wf2[i];
    if (tid < D) bs[tid] = b[tid];
    __syncthreads();

    int lane = tid & 31;
    int warp = tid >> 5;
    int wpb  = blockDim.x >> 5;

    for (int node = blockIdx.x * wpb + warp; node < n; node += gridDim.x * wpb) {
        float s = inv_in[node];
        float2 xv = reinterpret_cast<const float2*>(agg + (long)node * D)[lane];
        xv.x *= s; xv.y *= s;

        float accx = bs[2 * lane];
        float accy = bs[2 * lane + 1];

        #pragma unroll
        for (int k2 = 0; k2 < 32; ++k2) {
            float xk0 = __shfl_sync(0xffffffffu, xv.x, k2);
            float xk1 = __shfl_sync(0xffffffffu, xv.y, k2);
            float2 w0 = Ws[2 * k2][lane];
            float2 w1 = Ws[2 * k2 + 1][lane];
            accx = fmaf(xk0, w0.x, accx);
            accx = fmaf(xk1, w1.x, accx);
            accy = fmaf(xk0, w0.y, accy);
            accy = fmaf(xk1, w1.y, accy);
        }
        accx = fmaxf(accx, 0.f);
        accy = fmaxf(accy, 0.f);

        reinterpret_cast<float2*>(cat_out + (long)node * CAT_STRIDE)[lane]
            = make_float2(accx, accy);

        float ssum = accx + accy;
        #pragma unroll
        for (int o = 16; o; o >>= 1)
            ssum += __shfl_xor_sync(0xffffffffu, ssum, o);
        if (lane == 0) pool_out[node] = ssum;
    }
}

// ---------------------------------------------------------------------------
extern "C" void kernel_launch(void* const* d_in, const int* in_sizes, int n_in,
                              void* d_out, int out_size) {
    const float* node_feat = (const float*)d_in[0];
    const int*   src       = (const int*)  d_in[1];
    const int*   dst       = (const int*)  d_in[2];
    // d_in[3] = graph_len (unused; N comes from node_feat size)
    const float* W[3] = { (const float*)d_in[4], (const float*)d_in[6], (const float*)d_in[8] };
    const float* B[3] = { (const float*)d_in[5], (const float*)d_in[7], (const float*)d_in[9] };

    const int n = in_sizes[0] / D;
    const int e = in_sizes[1];

    float* out = (float*)d_out;
    float* pool_base = out;            // [3*n] : layer-l segment at l*n
    float* cat_base  = out + 3 * (long)n;  // [n, 192]

    float* agg;
    float* inv_out;
    float* inv_in;
    cudaGetSymbolAddress((void**)&agg,     g_agg);
    cudaGetSymbolAddress((void**)&inv_out, g_inv_out);
    cudaGetSymbolAddress((void**)&inv_in,  g_inv_in);

    const int T = 256;

    // degrees -> inv-sqrt norms (once)
    zero_deg_kernel<<<(n + T - 1) / T, T>>>(inv_out, inv_in, n);
    deg_count_kernel<<<(e + T - 1) / T, T>>>(src, dst, inv_out, inv_in, e);
    make_inv_kernel<<<(n + T - 1) / T, T>>>(inv_out, inv_in, n);

    const long agg4 = (long)n * D / 4;

    for (int l = 0; l < 3; ++l) {
        // zero agg
        zero_f4_kernel<<<(int)((agg4 + T - 1) / T), T>>>((float4*)agg, (int)agg4);

        // scatter-add: x = node_feat (stride 64) for l=0, else previous layer's
        // output read straight from xs_cat (stride 192)
        const float* x      = (l == 0) ? node_feat : (cat_base + (l - 1) * D);
        const int    xstrid = (l == 0) ? D : CAT_STRIDE;
        long threads = (long)e * 16;
        scatter_kernel<<<(int)((threads + T - 1) / T), T>>>(x, xstrid, src, dst,
                                                            inv_out, agg, e);

        // dense + relu + writeout (cat block l, pool segment l)
        int blocks = (n + (T / 32) - 1) / (T / 32);
        dense_kernel<<<blocks, T>>>(agg, inv_in, W[l], B[l],
                                    cat_base + l * D, pool_base + (long)l * n, n);
    }
}

// round 2
// speedup vs baseline: 1.0258x; 1.0258x over previous
#include <cuda_runtime.h>
#include <cuda_bf16.h>

#define MAX_N 100000
#define MAX_E 1600000
#define D 64
#define CAT_STRIDE 192  // 3*D

// Scratch (device globals — no allocation allowed)
__device__ int   g_deg_out[MAX_N];
__device__ int   g_deg_in[MAX_N];
__device__ int   g_offs[MAX_N];      // CSR row starts (by dst)
__device__ int   g_cursor[MAX_N];    // placement cursors
__device__ int   g_csr_src[MAX_E];   // src node per CSR slot
__device__ float g_csr_scale[MAX_E]; // inv_out[src] per CSR slot
__device__ float g_inv_out[MAX_N];
__device__ float g_inv_in[MAX_N];

// ---------------------------------------------------------------------------
__global__ void zero_deg_kernel(int* __restrict__ a, int* __restrict__ b, int n) {
    int i = blockIdx.x * blockDim.x + threadIdx.x;
    if (i < n) { a[i] = 0; b[i] = 0; }
}

__global__ void deg_count_kernel(const int* __restrict__ src, const int* __restrict__ dst,
                                 int* __restrict__ dout, int* __restrict__ din, int e) {
    int i = blockIdx.x * blockDim.x + threadIdx.x;
    if (i < e) {
        atomicAdd(&dout[src[i]], 1);
        atomicAdd(&din[dst[i]], 1);
    }
}

__global__ void make_inv_kernel(const int* __restrict__ dout, const int* __restrict__ din,
                                float* __restrict__ iout, float* __restrict__ iin, int n) {
    int i = blockIdx.x * blockDim.x + threadIdx.x;
    if (i < n) {
        iout[i] = rsqrtf((float)max(dout[i], 1));
        iin[i]  = rsqrtf((float)max(din[i], 1));
    }
}

// Single-block exclusive scan of deg_in -> offs (and cursor copy).
// 1024 threads, each owning a contiguous chunk.
__global__ void scan_kernel(const int* __restrict__ deg, int* __restrict__ offs,
                            int* __restrict__ cursor, int n) {
    __shared__ int warpsums[32];
    const int T = 1024;
    int per = (n + T - 1) / T;
    int start = threadIdx.x * per;
    int end   = min(start + per, n);

    int s = 0;
    for (int i = start; i < end; ++i) s += deg[i];

    int lane = threadIdx.x & 31;
    int w    = threadIdx.x >> 5;
    int v = s;
    #pragma unroll
    for (int o = 1; o < 32; o <<= 1) {
        int t = __shfl_up_sync(0xffffffffu, v, o);
        if (lane >= o) v += t;
    }
    if (lane == 31) warpsums[w] = v;
    __syncthreads();
    if (w == 0) {
        int t = warpsums[lane];
        #pragma unroll
        for (int o = 1; o < 32; o <<= 1) {
            int u = __shfl_up_sync(0xffffffffu, t, o);
            if (lane >= o) t += u;
        }
        warpsums[lane] = t;
    }
    __syncthreads();

    int run = v - s + (w > 0 ? warpsums[w - 1] : 0);  // exclusive prefix for chunk
    for (int i = start; i < end; ++i) {
        offs[i] = run;
        cursor[i] = run;
        run += deg[i];
    }
}

// Place edges into CSR slots (order within a row is nondeterministic; fp sums
// only differ at ~1e-7, far below the 1e-3 threshold).
__global__ void place_kernel(const int* __restrict__ src, const int* __restrict__ dst,
                             const float* __restrict__ inv_out,
                             int* __restrict__ cursor,
                             int* __restrict__ csr_src, float* __restrict__ csr_scale, int e) {
    int i = blockIdx.x * blockDim.x + threadIdx.x;
    if (i < e) {
        int s = src[i];
        int p = atomicAdd(&cursor[dst[i]], 1);
        csr_src[p]   = s;
        csr_scale[p] = __ldg(&inv_out[s]);
    }
}

// ---------------------------------------------------------------------------
// Fused layer: per dst node (one warp):
//   acc = sum_{e in CSR row} x[src_e] * scale_e          (pull gather)
//   acc *= inv_in[node]
//   y = relu(acc @ W + b)   -> cat_out (stride 192), rowsum -> pool_out
__global__ void layer_kernel(const float* __restrict__ x, int xstride2, // stride in float2
                             const int* __restrict__ offs, const int* __restrict__ degs,
                             const int* __restrict__ csr_src, const float* __restrict__ csr_scale,
                             const float* __restrict__ inv_in,
                             const float* __restrict__ W, const float* __restrict__ b,
                             float* __restrict__ cat_out, float* __restrict__ pool_out,
                             int n) {
    __shared__ float2 Ws[D][32];   // Ws[k][j] = (W[k][2j], W[k][2j+1])
    __shared__ float  bs[D];

    int tid = threadIdx.x;
    const float2* Wf2 = reinterpret_cast<const float2*>(W);
    for (int i = tid; i < D * 32; i += blockDim.x)
        Ws[i >> 5][i & 31] = Wf2[i];
    if (tid < D) bs[tid] = b[tid];
    __syncthreads();

    int lane = tid & 31;
    int warp = tid >> 5;
    int wpb  = blockDim.x >> 5;
    int node = blockIdx.x * wpb + warp;
    if (node >= n) return;

    const float2* __restrict__ x2 = reinterpret_cast<const float2*>(x);

    int rs  = offs[node];
    int deg = degs[node];

    float ax = 0.f, ay = 0.f;
    for (int k = 0; k < deg; k += 32) {
        int nk = min(32, deg - k);
        int   sidx = 0;
        float sc   = 0.f;
        if (lane < nk) {
            sidx = csr_src[rs + k + lane];
            sc   = csr_scale[rs + k + lane];
        }
        int j = 0;
        // unroll by 2 to expose load-level parallelism
        for (; j + 2 <= nk; j += 2) {
            int   s0 = __shfl_sync(0xffffffffu, sidx, j);
            float c0 = __shfl_sync(0xffffffffu, sc,   j);
            int   s1 = __shfl_sync(0xffffffffu, sidx, j + 1);
            float c1 = __shfl_sync(0xffffffffu, sc,   j + 1);
            float2 v0 = x2[(long)s0 * xstride2 + lane];
            float2 v1 = x2[(long)s1 * xstride2 + lane];
            ax = fmaf(v0.x, c0, ax); ay = fmaf(v0.y, c0, ay);
            ax = fmaf(v1.x, c1, ax); ay = fmaf(v1.y, c1, ay);
        }
        for (; j < nk; ++j) {
            int   s0 = __shfl_sync(0xffffffffu, sidx, j);
            float c0 = __shfl_sync(0xffffffffu, sc,   j);
            float2 v0 = x2[(long)s0 * xstride2 + lane];
            ax = fmaf(v0.x, c0, ax); ay = fmaf(v0.y, c0, ay);
        }
    }

    float si = inv_in[node];
    ax *= si; ay *= si;

    // 64x64 GEMM via warp shfl broadcast: lane holds input cols (2lane, 2lane+1)
    float accx = bs[2 * lane];
    float accy = bs[2 * lane + 1];
    #pragma unroll
    for (int k2 = 0; k2 < 32; ++k2) {
        float xk0 = __shfl_sync(0xffffffffu, ax, k2);
        float xk1 = __shfl_sync(0xffffffffu, ay, k2);
        float2 w0 = Ws[2 * k2][lane];
        float2 w1 = Ws[2 * k2 + 1][lane];
        accx = fmaf(xk0, w0.x, accx);
        accx = fmaf(xk1, w1.x, accx);
        accy = fmaf(xk0, w0.y, accy);
        accy = fmaf(xk1, w1.y, accy);
    }
    accx = fmaxf(accx, 0.f);
    accy = fmaxf(accy, 0.f);

    reinterpret_cast<float2*>(cat_out + (long)node * CAT_STRIDE)[lane]
        = make_float2(accx, accy);

    float ssum = accx + accy;
    #pragma unroll
    for (int o = 16; o; o >>= 1)
        ssum += __shfl_xor_sync(0xffffffffu, ssum, o);
    if (lane == 0) pool_out[node] = ssum;
}

// ---------------------------------------------------------------------------
extern "C" void kernel_launch(void* const* d_in, const int* in_sizes, int n_in,
                              void* d_out, int out_size) {
    const float* node_feat = (const float*)d_in[0];
    const int*   src       = (const int*)  d_in[1];
    const int*   dst       = (const int*)  d_in[2];
    const float* W[3] = { (const float*)d_in[4], (const float*)d_in[6], (const float*)d_in[8] };
    const float* B[3] = { (const float*)d_in[5], (const float*)d_in[7], (const float*)d_in[9] };

    const int n = in_sizes[0] / D;
    const int e = in_sizes[1];

    float* out = (float*)d_out;
    float* pool_base = out;                 // [3n]
    float* cat_base  = out + 3 * (long)n;   // [n, 192]

    int *deg_out, *deg_in, *offs, *cursor, *csr_src;
    float *csr_scale, *inv_out, *inv_in;
    cudaGetSymbolAddress((void**)&deg_out,   g_deg_out);
    cudaGetSymbolAddress((void**)&deg_in,    g_deg_in);
    cudaGetSymbolAddress((void**)&offs,      g_offs);
    cudaGetSymbolAddress((void**)&cursor,    g_cursor);
    cudaGetSymbolAddress((void**)&csr_src,   g_csr_src);
    cudaGetSymbolAddress((void**)&csr_scale, g_csr_scale);
    cudaGetSymbolAddress((void**)&inv_out,   g_inv_out);
    cudaGetSymbolAddress((void**)&inv_in,    g_inv_in);

    const int T = 256;

    // --- CSR build (once per launch) ---
    zero_deg_kernel<<<(n + T - 1) / T, T>>>(deg_out, deg_in, n);
    deg_count_kernel<<<(e + T - 1) / T, T>>>(src, dst, deg_out, deg_in, e);
    make_inv_kernel<<<(n + T - 1) / T, T>>>(deg_out, deg_in, inv_out, inv_in, n);
    scan_kernel<<<1, 1024>>>(deg_in, offs, cursor, n);
    place_kernel<<<(e + T - 1) / T, T>>>(src, dst, inv_out, cursor, csr_src, csr_scale, e);

    // --- 3 fused layers ---
    const int wpb = T / 32;
    const int blocks = (n + wpb - 1) / wpb;
    for (int l = 0; l < 3; ++l) {
        const float* x    = (l == 0) ? node_feat : (cat_base + (l - 1) * D);
        const int xstride2 = ((l == 0) ? D : CAT_STRIDE) / 2;
        layer_kernel<<<blocks, T>>>(x, xstride2, offs, deg_in, csr_src, csr_scale,
                                    inv_in, W[l], B[l],
                                    cat_base + l * D, pool_base + (long)l * n, n);
    }
}

// round 3
// speedup vs baseline: 1.3303x; 1.2968x over previous
#include <cuda_runtime.h>
#include <cuda_bf16.h>

#define MAX_N 100000
#define MAX_E 1600000
#define D 64
#define CAT_STRIDE 192  // 3*D
#define TILE 1024       // scan tile (elements)
#define MAX_TILES ((MAX_N + TILE - 1) / TILE)

// Scratch (device globals — no allocation allowed)
__device__ int   g_deg_out[MAX_N];
__device__ int   g_deg_in[MAX_N];
__device__ int   g_offs[MAX_N];      // CSR row starts (by dst)
__device__ int   g_cursor[MAX_N];    // placement cursors
__device__ int   g_csr_src[MAX_E];   // src node per CSR slot
__device__ float g_csr_scale[MAX_E]; // inv_out[src] per CSR slot
__device__ float g_inv_out[MAX_N];
__device__ float g_inv_in[MAX_N];
__device__ int   g_tsums[MAX_TILES]; // per-tile degree sums
__device__ int   g_toffs[MAX_TILES]; // exclusive scan of tile sums

// ---------------------------------------------------------------------------
__global__ void zero_deg_kernel(int* __restrict__ a, int* __restrict__ b, int n) {
    int i = blockIdx.x * blockDim.x + threadIdx.x;
    if (i < n) { a[i] = 0; b[i] = 0; }
}

__global__ void deg_count_kernel(const int* __restrict__ src, const int* __restrict__ dst,
                                 int* __restrict__ dout, int* __restrict__ din, int e) {
    int i = blockIdx.x * blockDim.x + threadIdx.x;
    if (i < e) {
        atomicAdd(&dout[src[i]], 1);
        atomicAdd(&din[dst[i]], 1);
    }
}

__global__ void make_inv_kernel(const int* __restrict__ dout, const int* __restrict__ din,
                                float* __restrict__ iout, float* __restrict__ iin, int n) {
    int i = blockIdx.x * blockDim.x + threadIdx.x;
    if (i < n) {
        iout[i] = rsqrtf((float)max(dout[i], 1));
        iin[i]  = rsqrtf((float)max(din[i], 1));
    }
}

// ---------------------------------------------------------------------------
// Parallel scan, stage 1: per-tile sums. 256 threads/block, 4 elems/thread.
__global__ void tile_sum_kernel(const int* __restrict__ deg, int* __restrict__ tsums, int n) {
    __shared__ int wsum[8];
    int base = blockIdx.x * TILE + threadIdx.x * 4;
    int s = 0;
    #pragma unroll
    for (int j = 0; j < 4; ++j) {
        int i = base + j;
        if (i < n) s += deg[i];
    }
    #pragma unroll
    for (int o = 16; o; o >>= 1) s += __shfl_xor_sync(0xffffffffu, s, o);
    int lane = threadIdx.x & 31, w = threadIdx.x >> 5;
    if (lane == 0) wsum[w] = s;
    __syncthreads();
    if (threadIdx.x == 0) {
        int t = 0;
        #pragma unroll
        for (int j = 0; j < 8; ++j) t += wsum[j];
        tsums[blockIdx.x] = t;
    }
}

// Stage 2: exclusive scan of tile sums (ntiles <= 1024), one block.
__global__ void tile_offs_kernel(const int* __restrict__ tsums, int* __restrict__ toffs,
                                 int ntiles) {
    __shared__ int wsums[32];
    int tid = threadIdx.x;
    int v = (tid < ntiles) ? tsums[tid] : 0;
    int lane = tid & 31, w = tid >> 5;
    int inc = v;
    #pragma unroll
    for (int o = 1; o < 32; o <<= 1) {
        int t = __shfl_up_sync(0xffffffffu, inc, o);
        if (lane >= o) inc += t;
    }
    if (lane == 31) wsums[w] = inc;
    __syncthreads();
    if (w == 0) {
        int t = (lane < 32) ? wsums[lane] : 0;
        #pragma unroll
        for (int o = 1; o < 32; o <<= 1) {
            int u = __shfl_up_sync(0xffffffffu, t, o);
            if (lane >= o) t += u;
        }
        wsums[lane] = t;
    }
    __syncthreads();
    int excl = inc - v + (w > 0 ? wsums[w - 1] : 0);
    if (tid < ntiles) toffs[tid] = excl;
}

// Stage 3: per-tile rescan with tile offset -> offs, cursor.
__global__ void tile_scan_kernel(const int* __restrict__ deg, const int* __restrict__ toffs,
                                 int* __restrict__ offs, int* __restrict__ cursor, int n) {
    __shared__ int wsums[8];
    int tid = threadIdx.x;
    int base = blockIdx.x * TILE + tid * 4;
    int d[4];
    int s = 0;
    #pragma unroll
    for (int j = 0; j < 4; ++j) {
        int i = base + j;
        d[j] = (i < n) ? deg[i] : 0;
        s += d[j];
    }
    int lane = tid & 31, w = tid >> 5;
    int inc = s;
    #pragma unroll
    for (int o = 1; o < 32; o <<= 1) {
        int t = __shfl_up_sync(0xffffffffu, inc, o);
        if (lane >= o) inc += t;
    }
    if (lane == 31) wsums[w] = inc;
    __syncthreads();
    if (w == 0 && lane < 8) {
        int t = wsums[lane];
        #pragma unroll
        for (int o = 1; o < 8; o <<= 1) {
            int u = __shfl_up_sync(0xffu, t, o);
            if (lane >= o) t += u;
        }
        wsums[lane] = t;
    }
    __syncthreads();
    int run = toffs[blockIdx.x] + (inc - s) + (w > 0 ? wsums[w - 1] : 0);
    #pragma unroll
    for (int j = 0; j < 4; ++j) {
        int i = base + j;
        if (i < n) { offs[i] = run; cursor[i] = run; }
        run += d[j];
    }
}

// Place edges into CSR slots (order within a row is nondeterministic; fp sums
// only differ at ~1e-7, far below the 1e-3 threshold).
__global__ void place_kernel(const int* __restrict__ src, const int* __restrict__ dst,
                             const float* __restrict__ inv_out,
                             int* __restrict__ cursor,
                             int* __restrict__ csr_src, float* __restrict__ csr_scale, int e) {
    int i = blockIdx.x * blockDim.x + threadIdx.x;
    if (i < e) {
        int s = src[i];
        int p = atomicAdd(&cursor[dst[i]], 1);
        csr_src[p]   = s;
        csr_scale[p] = __ldg(&inv_out[s]);
    }
}

// ---------------------------------------------------------------------------
// Fused layer: per dst node (one warp):
//   acc = sum_{e in CSR row} x[src_e] * scale_e          (pull gather)
//   acc *= inv_in[node]
//   y = relu(acc @ W + b)   -> cat_out (stride 192), rowsum -> pool_out
__global__ void layer_kernel(const float* __restrict__ x, int xstride2, // stride in float2
                             const int* __restrict__ offs, const int* __restrict__ degs,
                             const int* __restrict__ csr_src, const float* __restrict__ csr_scale,
                             const float* __restrict__ inv_in,
                             const float* __restrict__ W, const float* __restrict__ b,
                             float* __restrict__ cat_out, float* __restrict__ pool_out,
                             int n) {
    __shared__ float2 Ws[D][32];   // Ws[k][j] = (W[k][2j], W[k][2j+1])
    __shared__ float  bs[D];

    int tid = threadIdx.x;
    const float2* Wf2 = reinterpret_cast<const float2*>(W);
    for (int i = tid; i < D * 32; i += blockDim.x)
        Ws[i >> 5][i & 31] = Wf2[i];
    if (tid < D) bs[tid] = b[tid];
    __syncthreads();

    int lane = tid & 31;
    int warp = tid >> 5;
    int wpb  = blockDim.x >> 5;
    int node = blockIdx.x * wpb + warp;
    if (node >= n) return;

    const float2* __restrict__ x2 = reinterpret_cast<const float2*>(x);

    int rs  = offs[node];
    int deg = degs[node];

    float ax = 0.f, ay = 0.f;
    for (int k = 0; k < deg; k += 32) {
        int nk = min(32, deg - k);
        int   sidx = 0;
        float sc   = 0.f;
        if (lane < nk) {
            sidx = csr_src[rs + k + lane];
            sc   = csr_scale[rs + k + lane];
        }
        int j = 0;
        // unroll by 4 for memory-level parallelism (4 independent row loads)
        for (; j + 4 <= nk; j += 4) {
            int   s0 = __shfl_sync(0xffffffffu, sidx, j);
            int   s1 = __shfl_sync(0xffffffffu, sidx, j + 1);
            int   s2 = __shfl_sync(0xffffffffu, sidx, j + 2);
            int   s3 = __shfl_sync(0xffffffffu, sidx, j + 3);
            float c0 = __shfl_sync(0xffffffffu, sc, j);
            float c1 = __shfl_sync(0xffffffffu, sc, j + 1);
            float c2 = __shfl_sync(0xffffffffu, sc, j + 2);
            float c3 = __shfl_sync(0xffffffffu, sc, j + 3);
            float2 v0 = x2[(long)s0 * xstride2 + lane];
            float2 v1 = x2[(long)s1 * xstride2 + lane];
            float2 v2 = x2[(long)s2 * xstride2 + lane];
            float2 v3 = x2[(long)s3 * xstride2 + lane];
            ax = fmaf(v0.x, c0, ax); ay = fmaf(v0.y, c0, ay);
            ax = fmaf(v1.x, c1, ax); ay = fmaf(v1.y, c1, ay);
            ax = fmaf(v2.x, c2, ax); ay = fmaf(v2.y, c2, ay);
            ax = fmaf(v3.x, c3, ax); ay = fmaf(v3.y, c3, ay);
        }
        for (; j < nk; ++j) {
            int   s0 = __shfl_sync(0xffffffffu, sidx, j);
            float c0 = __shfl_sync(0xffffffffu, sc,   j);
            float2 v0 = x2[(long)s0 * xstride2 + lane];
            ax = fmaf(v0.x, c0, ax); ay = fmaf(v0.y, c0, ay);
        }
    }

    float si = inv_in[node];
    ax *= si; ay *= si;

    // 64x64 GEMM via warp shfl broadcast: lane holds input cols (2lane, 2lane+1)
    float accx = bs[2 * lane];
    float accy = bs[2 * lane + 1];
    #pragma unroll
    for (int k2 = 0; k2 < 32; ++k2) {
        float xk0 = __shfl_sync(0xffffffffu, ax, k2);
        float xk1 = __shfl_sync(0xffffffffu, ay, k2);
        float2 w0 = Ws[2 * k2][lane];
        float2 w1 = Ws[2 * k2 + 1][lane];
        accx = fmaf(xk0, w0.x, accx);
        accx = fmaf(xk1, w1.x, accx);
        accy = fmaf(xk0, w0.y, accy);
        accy = fmaf(xk1, w1.y, accy);
    }
    accx = fmaxf(accx, 0.f);
    accy = fmaxf(accy, 0.f);

    reinterpret_cast<float2*>(cat_out + (long)node * CAT_STRIDE)[lane]
        = make_float2(accx, accy);

    float ssum = accx + accy;
    #pragma unroll
    for (int o = 16; o; o >>= 1)
        ssum += __shfl_xor_sync(0xffffffffu, ssum, o);
    if (lane == 0) pool_out[node] = ssum;
}

// ---------------------------------------------------------------------------
extern "C" void kernel_launch(void* const* d_in, const int* in_sizes, int n_in,
                              void* d_out, int out_size) {
    const float* node_feat = (const float*)d_in[0];
    const int*   src       = (const int*)  d_in[1];
    const int*   dst       = (const int*)  d_in[2];
    const float* W[3] = { (const float*)d_in[4], (const float*)d_in[6], (const float*)d_in[8] };
    const float* B[3] = { (const float*)d_in[5], (const float*)d_in[7], (const float*)d_in[9] };

    const int n = in_sizes[0] / D;
    const int e = in_sizes[1];

    float* out = (float*)d_out;
    float* pool_base = out;                 // [3n]
    float* cat_base  = out + 3 * (long)n;   // [n, 192]

    int *deg_out, *deg_in, *offs, *cursor, *csr_src, *tsums, *toffs;
    float *csr_scale, *inv_out, *inv_in;
    cudaGetSymbolAddress((void**)&deg_out,   g_deg_out);
    cudaGetSymbolAddress((void**)&deg_in,    g_deg_in);
    cudaGetSymbolAddress((void**)&offs,      g_offs);
    cudaGetSymbolAddress((void**)&cursor,    g_cursor);
    cudaGetSymbolAddress((void**)&csr_src,   g_csr_src);
    cudaGetSymbolAddress((void**)&csr_scale, g_csr_scale);
    cudaGetSymbolAddress((void**)&inv_out,   g_inv_out);
    cudaGetSymbolAddress((void**)&inv_in,    g_inv_in);
    cudaGetSymbolAddress((void**)&tsums,     g_tsums);
    cudaGetSymbolAddress((void**)&toffs,     g_toffs);

    const int T = 256;
    const int ntiles = (n + TILE - 1) / TILE;

    // --- CSR build (parallel scan) ---
    zero_deg_kernel<<<(n + T - 1) / T, T>>>(deg_out, deg_in, n);
    deg_count_kernel<<<(e + T - 1) / T, T>>>(src, dst, deg_out, deg_in, e);
    make_inv_kernel<<<(n + T - 1) / T, T>>>(deg_out, deg_in, inv_out, inv_in, n);
    tile_sum_kernel<<<ntiles, 256>>>(deg_in, tsums, n);
    tile_offs_kernel<<<1, 1024>>>(tsums, toffs, ntiles);
    tile_scan_kernel<<<ntiles, 256>>>(deg_in, toffs, offs, cursor, n);
    place_kernel<<<(e + T - 1) / T, T>>>(src, dst, inv_out, cursor, csr_src, csr_scale, e);

    // --- 3 fused layers ---
    const int wpb = T / 32;
    const int blocks = (n + wpb - 1) / wpb;
    for (int l = 0; l < 3; ++l) {
        const float* x    = (l == 0) ? node_feat : (cat_base + (l - 1) * D);
        const int xstride2 = ((l == 0) ? D : CAT_STRIDE) / 2;
        layer_kernel<<<blocks, T>>>(x, xstride2, offs, deg_in, csr_src, csr_scale,
                                    inv_in, W[l], B[l],
                                    cat_base + l * D, pool_base + (long)l * n, n);
    }
}

// round 4
// speedup vs baseline: 1.5087x; 1.1341x over previous
#include <cuda_runtime.h>
#include <cuda_bf16.h>

#define MAX_N 100000
#define MAX_E 1600000
#define D 64
#define CAT_STRIDE 192  // 3*D
#define TILE 1024       // scan tile (elements)
#define MAX_TILES ((MAX_N + TILE - 1) / TILE)
#define NPB 64          // nodes per block in fused layer
#define XS_STRIDE 66    // padded smem row stride (floats)

typedef unsigned long long u64;

// Scratch (device globals — no allocation allowed)
__device__ int   g_deg_out[MAX_N];
__device__ int   g_deg_in[MAX_N];
__device__ int   g_offs[MAX_N];
__device__ int   g_cursor[MAX_N];
__device__ int2  g_csr[MAX_E];       // (src, inv_out[src] bits)
__device__ float g_inv_out[MAX_N];
__device__ float g_inv_in[MAX_N];
__device__ int   g_tsums[MAX_TILES];
__device__ int   g_toffs[MAX_TILES];

// ---------------------------------------------------------------------------
// f32x2 packed helpers (sm_10x)
__device__ __forceinline__ u64 pk2(float a, float b) {
    u64 r; asm("mov.b64 %0, {%1, %2};" : "=l"(r) : "f"(a), "f"(b)); return r;
}
__device__ __forceinline__ u64 dupb(int bits) {
    u64 r; asm("mov.b64 %0, {%1, %2};" : "=l"(r) : "r"(bits), "r"(bits)); return r;
}
__device__ __forceinline__ u64 fma2(u64 a, u64 b, u64 c) {
    u64 d; asm("fma.rn.f32x2 %0, %1, %2, %3;" : "=l"(d) : "l"(a), "l"(b), "l"(c)); return d;
}
__device__ __forceinline__ u64 add2(u64 a, u64 b) {
    u64 d; asm("add.rn.f32x2 %0, %1, %2;" : "=l"(d) : "l"(a), "l"(b)); return d;
}
__device__ __forceinline__ float2 up2(u64 a) {
    float2 f; asm("mov.b64 {%0, %1}, %2;" : "=f"(f.x), "=f"(f.y) : "l"(a)); return f;
}

// ---------------------------------------------------------------------------
__global__ void zero_deg_kernel(int* __restrict__ a, int* __restrict__ b, int n) {
    int i = blockIdx.x * blockDim.x + threadIdx.x;
    if (i < n) { a[i] = 0; b[i] = 0; }
}

__global__ void deg_count_kernel(const int* __restrict__ src, const int* __restrict__ dst,
                                 int* __restrict__ dout, int* __restrict__ din, int e) {
    int i = blockIdx.x * blockDim.x + threadIdx.x;
    if (i < e) {
        atomicAdd(&dout[src[i]], 1);
        atomicAdd(&din[dst[i]], 1);
    }
}

__global__ void make_inv_kernel(const int* __restrict__ dout, const int* __restrict__ din,
                                float* __restrict__ iout, float* __restrict__ iin, int n) {
    int i = blockIdx.x * blockDim.x + threadIdx.x;
    if (i < n) {
        iout[i] = rsqrtf((float)max(dout[i], 1));
        iin[i]  = rsqrtf((float)max(din[i], 1));
    }
}

// Parallel scan, stage 1: per-tile sums.
__global__ void tile_sum_kernel(const int* __restrict__ deg, int* __restrict__ tsums, int n) {
    __shared__ int wsum[8];
    int base = blockIdx.x * TILE + threadIdx.x * 4;
    int s = 0;
    #pragma unroll
    for (int j = 0; j < 4; ++j) {
        int i = base + j;
        if (i < n) s += deg[i];
    }
    #pragma unroll
    for (int o = 16; o; o >>= 1) s += __shfl_xor_sync(0xffffffffu, s, o);
    int lane = threadIdx.x & 31, w = threadIdx.x >> 5;
    if (lane == 0) wsum[w] = s;
    __syncthreads();
    if (threadIdx.x == 0) {
        int t = 0;
        #pragma unroll
        for (int j = 0; j < 8; ++j) t += wsum[j];
        tsums[blockIdx.x] = t;
    }
}

// Stage 2: exclusive scan of tile sums, one block.
__global__ void tile_offs_kernel(const int* __restrict__ tsums, int* __restrict__ toffs,
                                 int ntiles) {
    __shared__ int wsums[32];
    int tid = threadIdx.x;
    int v = (tid < ntiles) ? tsums[tid] : 0;
    int lane = tid & 31, w = tid >> 5;
    int inc = v;
    #pragma unroll
    for (int o = 1; o < 32; o <<= 1) {
        int t = __shfl_up_sync(0xffffffffu, inc, o);
        if (lane >= o) inc += t;
    }
    if (lane == 31) wsums[w] = inc;
    __syncthreads();
    if (w == 0) {
        int t = wsums[lane];
        #pragma unroll
        for (int o = 1; o < 32; o <<= 1) {
            int u = __shfl_up_sync(0xffffffffu, t, o);
            if (lane >= o) t += u;
        }
        wsums[lane] = t;
    }
    __syncthreads();
    int excl = inc - v + (w > 0 ? wsums[w - 1] : 0);
    if (tid < ntiles) toffs[tid] = excl;
}

// Stage 3: per-tile rescan with tile offset.
__global__ void tile_scan_kernel(const int* __restrict__ deg, const int* __restrict__ toffs,
                                 int* __restrict__ offs, int* __restrict__ cursor, int n) {
    __shared__ int wsums[8];
    int tid = threadIdx.x;
    int base = blockIdx.x * TILE + tid * 4;
    int d[4];
    int s = 0;
    #pragma unroll
    for (int j = 0; j < 4; ++j) {
        int i = base + j;
        d[j] = (i < n) ? deg[i] : 0;
        s += d[j];
    }
    int lane = tid & 31, w = tid >> 5;
    int inc = s;
    #pragma unroll
    for (int o = 1; o < 32; o <<= 1) {
        int t = __shfl_up_sync(0xffffffffu, inc, o);
        if (lane >= o) inc += t;
    }
    if (lane == 31) wsums[w] = inc;
    __syncthreads();
    if (w == 0 && lane < 8) {
        int t = wsums[lane];
        #pragma unroll
        for (int o = 1; o < 8; o <<= 1) {
            int u = __shfl_up_sync(0xffu, t, o);
            if (lane >= o) t += u;
        }
        wsums[lane] = t;
    }
    __syncthreads();
    int run = toffs[blockIdx.x] + (inc - s) + (w > 0 ? wsums[w - 1] : 0);
    #pragma unroll
    for (int j = 0; j < 4; ++j) {
        int i = base + j;
        if (i < n) { offs[i] = run; cursor[i] = run; }
        run += d[j];
    }
}

// Place edges into packed CSR slots.
__global__ void place_kernel(const int* __restrict__ src, const int* __restrict__ dst,
                             const float* __restrict__ inv_out,
                             int* __restrict__ cursor, int2* __restrict__ csr, int e) {
    int i = blockIdx.x * blockDim.x + threadIdx.x;
    if (i < e) {
        int s = src[i];
        int p = atomicAdd(&cursor[dst[i]], 1);
        csr[p] = make_int2(s, __float_as_int(__ldg(&inv_out[s])));
    }
}

// ---------------------------------------------------------------------------
// Fused layer, block-tiled:
//   Phase 1: 8 warps gather 8 nodes each (uniform csr loads, f32x2 acc),
//            scaled rows -> smem xs[64][66]
//   Phase 2: tiled GEMM: thread = (node, 16-col group); W in smem (swizzled),
//            relu + cat write (float4) + pool rowsum
__global__ void __launch_bounds__(256)
layer_kernel(const float* __restrict__ x, int xs2, // row stride in u64 units
             const int* __restrict__ offs, const int* __restrict__ degs,
             const int2* __restrict__ csr,
             const float* __restrict__ inv_in,
             const float* __restrict__ W, const float* __restrict__ b,
             float* __restrict__ cat_out, float* __restrict__ pool_out,
             int n) {
    __shared__ float  xs[NPB * XS_STRIDE];
    __shared__ float4 Ws[D * 16];        // swizzled: [k*16 + q*4 + (i^q)]
    __shared__ float  bs[D];

    int tid  = threadIdx.x;
    int lane = tid & 31;
    int warp = tid >> 5;

    // Load W with the q-XOR swizzle (kills q0/q2, q1/q3 bank collisions)
    const float4* W4 = reinterpret_cast<const float4*>(W);
    #pragma unroll
    for (int r = 0; r < 4; ++r) {
        int m = tid + 256 * r;           // 0..1023 = k*16 + j4
        int k = m >> 4, j4 = m & 15;
        int q = j4 >> 2, i = j4 & 3;
        Ws[(k << 4) + (q << 2) + (i ^ q)] = W4[m];
    }
    if (tid < D) bs[tid] = b[tid];

    const u64* __restrict__ xu = reinterpret_cast<const u64*>(x);
    int base = blockIdx.x * NPB;

    // ---- Phase 1: gather (warp-per-node, 8 nodes per warp) ----
    for (int s = 0; s < 8; ++s) {
        int local = (warp << 3) + s;
        int node  = base + local;
        if (node < n) {
            int rs  = offs[node];
            int deg = degs[node];
            u64 accA = 0ull, accB = 0ull;
            int j = 0;
            for (; j + 8 <= deg; j += 8) {
                int2 c0 = csr[rs + j + 0];
                int2 c1 = csr[rs + j + 1];
                int2 c2 = csr[rs + j + 2];
                int2 c3 = csr[rs + j + 3];
                int2 c4 = csr[rs + j + 4];
                int2 c5 = csr[rs + j + 5];
                int2 c6 = csr[rs + j + 6];
                int2 c7 = csr[rs + j + 7];
                u64 v0 = xu[(long)c0.x * xs2 + lane];
                u64 v1 = xu[(long)c1.x * xs2 + lane];
                u64 v2 = xu[(long)c2.x * xs2 + lane];
                u64 v3 = xu[(long)c3.x * xs2 + lane];
                u64 v4 = xu[(long)c4.x * xs2 + lane];
                u64 v5 = xu[(long)c5.x * xs2 + lane];
                u64 v6 = xu[(long)c6.x * xs2 + lane];
                u64 v7 = xu[(long)c7.x * xs2 + lane];
                accA = fma2(v0, dupb(c0.y), accA);
                accB = fma2(v1, dupb(c1.y), accB);
                accA = fma2(v2, dupb(c2.y), accA);
                accB = fma2(v3, dupb(c3.y), accB);
                accA = fma2(v4, dupb(c4.y), accA);
                accB = fma2(v5, dupb(c5.y), accB);
                accA = fma2(v6, dupb(c6.y), accA);
                accB = fma2(v7, dupb(c7.y), accB);
            }
            for (; j + 4 <= deg; j += 4) {
                int2 c0 = csr[rs + j + 0];
                int2 c1 = csr[rs + j + 1];
                int2 c2 = csr[rs + j + 2];
                int2 c3 = csr[rs + j + 3];
                u64 v0 = xu[(long)c0.x * xs2 + lane];
                u64 v1 = xu[(long)c1.x * xs2 + lane];
                u64 v2 = xu[(long)c2.x * xs2 + lane];
                u64 v3 = xu[(long)c3.x * xs2 + lane];
                accA = fma2(v0, dupb(c0.y), accA);
                accB = fma2(v1, dupb(c1.y), accB);
                accA = fma2(v2, dupb(c2.y), accA);
                accB = fma2(v3, dupb(c3.y), accB);
            }
            for (; j < deg; ++j) {
                int2 c0 = csr[rs + j];
                u64 v0 = xu[(long)c0.x * xs2 + lane];
                accA = fma2(v0, dupb(c0.y), accA);
            }
            float2 a = up2(add2(accA, accB));
            float si = inv_in[node];
            *reinterpret_cast<float2*>(&xs[local * XS_STRIDE + (lane << 1)])
                = make_float2(a.x * si, a.y * si);
        }
    }
    __syncthreads();

    // ---- Phase 2: tiled GEMM (thread = node ln, col group q of 16) ----
    int ln = tid >> 2;
    int q  = tid & 3;
    int node = base + ln;

    u64 acc[8];
    #pragma unroll
    for (int i = 0; i < 8; ++i)
        acc[i] = pk2(bs[(q << 4) + 2 * i], bs[(q << 4) + 2 * i + 1]);

    const float* xrow = &xs[ln * XS_STRIDE];
    const ulonglong2* Wsu = reinterpret_cast<const ulonglong2*>(Ws);

    #pragma unroll 8
    for (int k = 0; k < D; ++k) {
        float xk = xrow[k];
        u64 xx = pk2(xk, xk);
        int wb = (k << 4) + (q << 2);
        ulonglong2 w0 = Wsu[wb + (0 ^ q)];
        ulonglong2 w1 = Wsu[wb + (1 ^ q)];
        ulonglong2 w2 = Wsu[wb + (2 ^ q)];
        ulonglong2 w3 = Wsu[wb + (3 ^ q)];
        // un-swizzle: chunk index i = (s ^ q) where s is slot; mapping is an
        // involution, so slot (i^q) holds chunk i: w0 is chunk (0^q)^q = 0? No:
        // slot s holds chunk (s^q)... we loaded slots (i^q) which hold chunk i. OK:
        acc[2 * 0 + 0] = fma2(xx, w0.x, acc[0]);
        acc[2 * 0 + 1] = fma2(xx, w0.y, acc[1]);
        acc[2 * 1 + 0] = fma2(xx, w1.x, acc[2]);
        acc[2 * 1 + 1] = fma2(xx, w1.y, acc[3]);
        acc[2 * 2 + 0] = fma2(xx, w2.x, acc[4]);
        acc[2 * 2 + 1] = fma2(xx, w2.y, acc[5]);
        acc[2 * 3 + 0] = fma2(xx, w3.x, acc[6]);
        acc[2 * 3 + 1] = fma2(xx, w3.y, acc[7]);
    }
    // NOTE on swizzle correctness: writer stored chunk (k,q,i) at slot i^q;
    // reader fetches slot i^q for chunk i — consistent by involution.

    if (node < n) {
        float2 p0 = up2(acc[0]), p1 = up2(acc[1]), p2 = up2(acc[2]), p3 = up2(acc[3]);
        float2 p4 = up2(acc[4]), p5 = up2(acc[5]), p6 = up2(acc[6]), p7 = up2(acc[7]);
        float v[16] = { p0.x, p0.y, p1.x, p1.y, p2.x, p2.y, p3.x, p3.y,
                        p4.x, p4.y, p5.x, p5.y, p6.x, p6.y, p7.x, p7.y };
        float ssum = 0.f;
        #pragma unroll
        for (int i = 0; i < 16; ++i) {
            v[i] = fmaxf(v[i], 0.f);
            ssum += v[i];
        }
        float4* co = reinterpret_cast<float4*>(cat_out + (long)node * CAT_STRIDE + (q << 4));
        co[0] = make_float4(v[0],  v[1],  v[2],  v[3]);
        co[1] = make_float4(v[4],  v[5],  v[6],  v[7]);
        co[2] = make_float4(v[8],  v[9],  v[10], v[11]);
        co[3] = make_float4(v[12], v[13], v[14], v[15]);

        // combine 4 q-threads (lane bits 0..1)
        ssum += __shfl_xor_sync(0xffffffffu, ssum, 1);
        ssum += __shfl_xor_sync(0xffffffffu, ssum, 2);
        if (q == 0) pool_out[node] = ssum;
    }
}

// ---------------------------------------------------------------------------
extern "C" void kernel_launch(void* const* d_in, const int* in_sizes, int n_in,
                              void* d_out, int out_size) {
    const float* node_feat = (const float*)d_in[0];
    const int*   src       = (const int*)  d_in[1];
    const int*   dst       = (const int*)  d_in[2];
    const float* W[3] = { (const float*)d_in[4], (const float*)d_in[6], (const float*)d_in[8] };
    const float* B[3] = { (const float*)d_in[5], (const float*)d_in[7], (const float*)d_in[9] };

    const int n = in_sizes[0] / D;
    const int e = in_sizes[1];

    float* out = (float*)d_out;
    float* pool_base = out;                 // [3n]
    float* cat_base  = out + 3 * (long)n;   // [n, 192]

    int *deg_out, *deg_in, *offs, *cursor, *tsums, *toffs;
    int2 *csr;
    float *inv_out, *inv_in;
    cudaGetSymbolAddress((void**)&deg_out, g_deg_out);
    cudaGetSymbolAddress((void**)&deg_in,  g_deg_in);
    cudaGetSymbolAddress((void**)&offs,    g_offs);
    cudaGetSymbolAddress((void**)&cursor,  g_cursor);
    cudaGetSymbolAddress((void**)&csr,     g_csr);
    cudaGetSymbolAddress((void**)&inv_out, g_inv_out);
    cudaGetSymbolAddress((void**)&inv_in,  g_inv_in);
    cudaGetSymbolAddress((void**)&tsums,   g_tsums);
    cudaGetSymbolAddress((void**)&toffs,   g_toffs);

    const int T = 256;
    const int ntiles = (n + TILE - 1) / TILE;

    // --- CSR build ---
    zero_deg_kernel<<<(n + T - 1) / T, T>>>(deg_out, deg_in, n);
    deg_count_kernel<<<(e + T - 1) / T, T>>>(src, dst, deg_out, deg_in, e);
    make_inv_kernel<<<(n + T - 1) / T, T>>>(deg_out, deg_in, inv_out, inv_in, n);
    tile_sum_kernel<<<ntiles, 256>>>(deg_in, tsums, n);
    tile_offs_kernel<<<1, 1024>>>(tsums, toffs, ntiles);
    tile_scan_kernel<<<ntiles, 256>>>(deg_in, toffs, offs, cursor, n);
    place_kernel<<<(e + T - 1) / T, T>>>(src, dst, inv_out, cursor, csr, e);

    // --- 3 fused layers ---
    const int blocks = (n + NPB - 1) / NPB;
    for (int l = 0; l < 3; ++l) {
        const float* x  = (l == 0) ? node_feat : (cat_base + (l - 1) * D);
        const int   xs2 = ((l == 0) ? D : CAT_STRIDE) / 2;   // stride in u64 units
        layer_kernel<<<blocks, T>>>(x, xs2, offs, deg_in, csr, inv_in,
                                    W[l], B[l],
                                    cat_base + l * D, pool_base + (long)l * n, n);
    }
}

// round 5
// speedup vs baseline: 1.8949x; 1.2560x over previous
#include <cuda_runtime.h>
#include <cuda_bf16.h>

#define MAX_N 100000
#define MAX_E 1600000
#define D 64
#define CAT_STRIDE 192  // 3*D
#define TILE 1024       // scan tile (elements)
#define MAX_TILES ((MAX_N + TILE - 1) / TILE)
#define NPB 64          // nodes per block in GEMM kernel
#define XT_STRIDE 68    // transposed smem stride (floats, mult of 4)

typedef unsigned long long u64;

// Scratch (device globals — no allocation allowed)
__device__ int   g_deg_out[MAX_N];
__device__ int   g_deg_in[MAX_N];
__device__ int   g_offs[MAX_N];
__device__ int   g_cursor[MAX_N];
__device__ int2  g_csr[MAX_E];       // (src, inv_out[src] bits)
__device__ float g_inv_out[MAX_N];
__device__ float g_inv_in[MAX_N];
__device__ int   g_tsums[MAX_TILES];
__device__ int   g_toffs[MAX_TILES];
__device__ float g_agg[MAX_N * D];   // gather output (raw sums)

// ---------------------------------------------------------------------------
// f32x2 packed helpers (sm_10x)
__device__ __forceinline__ u64 pk2(float a, float b) {
    u64 r; asm("mov.b64 %0, {%1, %2};" : "=l"(r) : "f"(a), "f"(b)); return r;
}
__device__ __forceinline__ u64 dupb(int bits) {
    u64 r; asm("mov.b64 %0, {%1, %2};" : "=l"(r) : "r"(bits), "r"(bits)); return r;
}
__device__ __forceinline__ u64 fma2(u64 a, u64 b, u64 c) {
    u64 d; asm("fma.rn.f32x2 %0, %1, %2, %3;" : "=l"(d) : "l"(a), "l"(b), "l"(c)); return d;
}
__device__ __forceinline__ u64 add2(u64 a, u64 b) {
    u64 d; asm("add.rn.f32x2 %0, %1, %2;" : "=l"(d) : "l"(a), "l"(b)); return d;
}
__device__ __forceinline__ float2 up2(u64 a) {
    float2 f; asm("mov.b64 {%0, %1}, %2;" : "=f"(f.x), "=f"(f.y) : "l"(a)); return f;
}

// ---------------------------------------------------------------------------
__global__ void zero_deg_kernel(int* __restrict__ a, int* __restrict__ b, int n) {
    int i = blockIdx.x * blockDim.x + threadIdx.x;
    if (i < n) { a[i] = 0; b[i] = 0; }
}

__global__ void deg_count_kernel(const int* __restrict__ src, const int* __restrict__ dst,
                                 int* __restrict__ dout, int* __restrict__ din, int e) {
    int i = blockIdx.x * blockDim.x + threadIdx.x;
    if (i < e) {
        atomicAdd(&dout[src[i]], 1);
        atomicAdd(&din[dst[i]], 1);
    }
}

__global__ void make_inv_kernel(const int* __restrict__ dout, const int* __restrict__ din,
                                float* __restrict__ iout, float* __restrict__ iin, int n) {
    int i = blockIdx.x * blockDim.x + threadIdx.x;
    if (i < n) {
        iout[i] = rsqrtf((float)max(dout[i], 1));
        iin[i]  = rsqrtf((float)max(din[i], 1));
    }
}

// Parallel scan, stage 1: per-tile sums.
__global__ void tile_sum_kernel(const int* __restrict__ deg, int* __restrict__ tsums, int n) {
    __shared__ int wsum[8];
    int base = blockIdx.x * TILE + threadIdx.x * 4;
    int s = 0;
    #pragma unroll
    for (int j = 0; j < 4; ++j) {
        int i = base + j;
        if (i < n) s += deg[i];
    }
    #pragma unroll
    for (int o = 16; o; o >>= 1) s += __shfl_xor_sync(0xffffffffu, s, o);
    int lane = threadIdx.x & 31, w = threadIdx.x >> 5;
    if (lane == 0) wsum[w] = s;
    __syncthreads();
    if (threadIdx.x == 0) {
        int t = 0;
        #pragma unroll
        for (int j = 0; j < 8; ++j) t += wsum[j];
        tsums[blockIdx.x] = t;
    }
}

// Stage 2: exclusive scan of tile sums, one block.
__global__ void tile_offs_kernel(const int* __restrict__ tsums, int* __restrict__ toffs,
                                 int ntiles) {
    __shared__ int wsums[32];
    int tid = threadIdx.x;
    int v = (tid < ntiles) ? tsums[tid] : 0;
    int lane = tid & 31, w = tid >> 5;
    int inc = v;
    #pragma unroll
    for (int o = 1; o < 32; o <<= 1) {
        int t = __shfl_up_sync(0xffffffffu, inc, o);
        if (lane >= o) inc += t;
    }
    if (lane == 31) wsums[w] = inc;
    __syncthreads();
    if (w == 0) {
        int t = wsums[lane];
        #pragma unroll
        for (int o = 1; o < 32; o <<= 1) {
            int u = __shfl_up_sync(0xffffffffu, t, o);
            if (lane >= o) t += u;
        }
        wsums[lane] = t;
    }
    __syncthreads();
    int excl = inc - v + (w > 0 ? wsums[w - 1] : 0);
    if (tid < ntiles) toffs[tid] = excl;
}

// Stage 3: per-tile rescan with tile offset.
__global__ void tile_scan_kernel(const int* __restrict__ deg, const int* __restrict__ toffs,
                                 int* __restrict__ offs, int* __restrict__ cursor, int n) {
    __shared__ int wsums[8];
    int tid = threadIdx.x;
    int base = blockIdx.x * TILE + tid * 4;
    int d[4];
    int s = 0;
    #pragma unroll
    for (int j = 0; j < 4; ++j) {
        int i = base + j;
        d[j] = (i < n) ? deg[i] : 0;
        s += d[j];
    }
    int lane = tid & 31, w = tid >> 5;
    int inc = s;
    #pragma unroll
    for (int o = 1; o < 32; o <<= 1) {
        int t = __shfl_up_sync(0xffffffffu, inc, o);
        if (lane >= o) inc += t;
    }
    if (lane == 31) wsums[w] = inc;
    __syncthreads();
    if (w == 0 && lane < 8) {
        int t = wsums[lane];
        #pragma unroll
        for (int o = 1; o < 8; o <<= 1) {
            int u = __shfl_up_sync(0xffu, t, o);
            if (lane >= o) t += u;
        }
        wsums[lane] = t;
    }
    __syncthreads();
    int run = toffs[blockIdx.x] + (inc - s) + (w > 0 ? wsums[w - 1] : 0);
    #pragma unroll
    for (int j = 0; j < 4; ++j) {
        int i = base + j;
        if (i < n) { offs[i] = run; cursor[i] = run; }
        run += d[j];
    }
}

// Place edges into packed CSR slots.
__global__ void place_kernel(const int* __restrict__ src, const int* __restrict__ dst,
                             const float* __restrict__ inv_out,
                             int* __restrict__ cursor, int2* __restrict__ csr, int e) {
    int i = blockIdx.x * blockDim.x + threadIdx.x;
    if (i < e) {
        int s = src[i];
        int p = atomicAdd(&cursor[dst[i]], 1);
        csr[p] = make_int2(s, __float_as_int(__ldg(&inv_out[s])));
    }
}

// ---------------------------------------------------------------------------
// Gather: one warp per node. agg[node] = sum_e x[src_e] * scale_e (raw, no inv_in).
__global__ void __launch_bounds__(256)
gather_kernel(const float* __restrict__ x, int xs2,   // row stride in u64 units
              const int* __restrict__ offs, const int* __restrict__ degs,
              const int2* __restrict__ csr,
              u64* __restrict__ agg, int n) {
    int node = (blockIdx.x * blockDim.x + threadIdx.x) >> 5;
    int lane = threadIdx.x & 31;
    if (node >= n) return;

    const u64* __restrict__ xu = reinterpret_cast<const u64*>(x);
    int rs  = offs[node];
    int deg = degs[node];

    u64 accA = 0ull, accB = 0ull;
    int j = 0;
    for (; j + 8 <= deg; j += 8) {
        int2 c0 = csr[rs + j + 0];
        int2 c1 = csr[rs + j + 1];
        int2 c2 = csr[rs + j + 2];
        int2 c3 = csr[rs + j + 3];
        int2 c4 = csr[rs + j + 4];
        int2 c5 = csr[rs + j + 5];
        int2 c6 = csr[rs + j + 6];
        int2 c7 = csr[rs + j + 7];
        u64 v0 = xu[(long)c0.x * xs2 + lane];
        u64 v1 = xu[(long)c1.x * xs2 + lane];
        u64 v2 = xu[(long)c2.x * xs2 + lane];
        u64 v3 = xu[(long)c3.x * xs2 + lane];
        u64 v4 = xu[(long)c4.x * xs2 + lane];
        u64 v5 = xu[(long)c5.x * xs2 + lane];
        u64 v6 = xu[(long)c6.x * xs2 + lane];
        u64 v7 = xu[(long)c7.x * xs2 + lane];
        accA = fma2(v0, dupb(c0.y), accA);
        accB = fma2(v1, dupb(c1.y), accB);
        accA = fma2(v2, dupb(c2.y), accA);
        accB = fma2(v3, dupb(c3.y), accB);
        accA = fma2(v4, dupb(c4.y), accA);
        accB = fma2(v5, dupb(c5.y), accB);
        accA = fma2(v6, dupb(c6.y), accA);
        accB = fma2(v7, dupb(c7.y), accB);
    }
    for (; j + 4 <= deg; j += 4) {
        int2 c0 = csr[rs + j + 0];
        int2 c1 = csr[rs + j + 1];
        int2 c2 = csr[rs + j + 2];
        int2 c3 = csr[rs + j + 3];
        u64 v0 = xu[(long)c0.x * xs2 + lane];
        u64 v1 = xu[(long)c1.x * xs2 + lane];
        u64 v2 = xu[(long)c2.x * xs2 + lane];
        u64 v3 = xu[(long)c3.x * xs2 + lane];
        accA = fma2(v0, dupb(c0.y), accA);
        accB = fma2(v1, dupb(c1.y), accB);
        accA = fma2(v2, dupb(c2.y), accA);
        accB = fma2(v3, dupb(c3.y), accB);
    }
    for (; j < deg; ++j) {
        int2 c0 = csr[rs + j];
        u64 v0 = xu[(long)c0.x * xs2 + lane];
        accA = fma2(v0, dupb(c0.y), accA);
    }
    agg[(long)node * 32 + lane] = add2(accA, accB);
}

// ---------------------------------------------------------------------------
// GEMM: y = relu((agg * inv_in) @ W + b); block = 64 nodes, thread = 4n x 4c tile.
__global__ void __launch_bounds__(256)
gemm_kernel(const float* __restrict__ agg, const float* __restrict__ inv_in,
            const float* __restrict__ W, const float* __restrict__ b,
            float* __restrict__ cat_out, float* __restrict__ pool_out, int n) {
    __shared__ float  xs_t[D * XT_STRIDE];   // xs_t[k * 68 + node]
    __shared__ float4 Ws4[D * 16];           // Ws4[k*16 + c4] = W[k][4c4..4c4+3]
    __shared__ float  bs[D];

    int tid  = threadIdx.x;
    int base = blockIdx.x * NPB;

    // Stage W (plain layout; k-loop reads are broadcast-deduped, conflict-free)
    const float4* W4 = reinterpret_cast<const float4*>(W);
    #pragma unroll
    for (int r = 0; r < 4; ++r)
        Ws4[tid + 256 * r] = W4[tid + 256 * r];
    if (tid < D) bs[tid] = b[tid];

    // Stage x transposed: thread t covers node=t>>2, 16 cols (t&3)*16..+15
    {
        int node = base + (tid >> 2);
        int k16  = tid & 3;
        if (node < n) {
            float si = inv_in[node];
            const float4* af = reinterpret_cast<const float4*>(agg) + (long)node * 16;
            #pragma unroll
            for (int i = 0; i < 4; ++i) {
                float4 v = af[k16 * 4 + i];
                int k = k16 * 16 + i * 4;
                xs_t[(k + 0) * XT_STRIDE + (node - base)] = v.x * si;
                xs_t[(k + 1) * XT_STRIDE + (node - base)] = v.y * si;
                xs_t[(k + 2) * XT_STRIDE + (node - base)] = v.z * si;
                xs_t[(k + 3) * XT_STRIDE + (node - base)] = v.w * si;
            }
        }
    }
    __syncthreads();

    int c4 = tid & 15;        // col group: cols 4*c4 .. +3
    int ng = tid >> 4;        // node group: nodes base + 4*ng .. +3

    // acc[i][0] = cols (4c4, 4c4+1), acc[i][1] = cols (4c4+2, 4c4+3) for node i
    u64 acc[4][2];
    {
        u64 blo = pk2(bs[4 * c4 + 0], bs[4 * c4 + 1]);
        u64 bhi = pk2(bs[4 * c4 + 2], bs[4 * c4 + 3]);
        #pragma unroll
        for (int i = 0; i < 4; ++i) { acc[i][0] = blo; acc[i][1] = bhi; }
    }

    #pragma unroll 4
    for (int k = 0; k < D; ++k) {
        float4 w = Ws4[k * 16 + c4];
        u64 wlo = pk2(w.x, w.y);
        u64 whi = pk2(w.z, w.w);
        float4 xv = *reinterpret_cast<const float4*>(&xs_t[k * XT_STRIDE + 4 * ng]);
        u64 x0 = pk2(xv.x, xv.x);
        u64 x1 = pk2(xv.y, xv.y);
        u64 x2 = pk2(xv.z, xv.z);
        u64 x3 = pk2(xv.w, xv.w);
        acc[0][0] = fma2(x0, wlo, acc[0][0]); acc[0][1] = fma2(x0, whi, acc[0][1]);
        acc[1][0] = fma2(x1, wlo, acc[1][0]); acc[1][1] = fma2(x1, whi, acc[1][1]);
        acc[2][0] = fma2(x2, wlo, acc[2][0]); acc[2][1] = fma2(x2, whi, acc[2][1]);
        acc[3][0] = fma2(x3, wlo, acc[3][0]); acc[3][1] = fma2(x3, whi, acc[3][1]);
    }

    // Epilogue: relu, cat float4 stores, pool via half-warp shfl reduce over c4
    float psum[4];
    #pragma unroll
    for (int i = 0; i < 4; ++i) {
        float2 lo = up2(acc[i][0]);
        float2 hi = up2(acc[i][1]);
        float v0 = fmaxf(lo.x, 0.f), v1 = fmaxf(lo.y, 0.f);
        float v2 = fmaxf(hi.x, 0.f), v3 = fmaxf(hi.y, 0.f);
        psum[i] = (v0 + v1) + (v2 + v3);
        int node = base + 4 * ng + i;
        if (node < n) {
            *reinterpret_cast<float4*>(cat_out + (long)node * CAT_STRIDE + 4 * c4)
                = make_float4(v0, v1, v2, v3);
        }
    }
    // reduce across the 16 c4-threads (lanes differ only in low 4 bits)
    #pragma unroll
    for (int o = 1; o < 16; o <<= 1) {
        #pragma unroll
        for (int i = 0; i < 4; ++i)
            psum[i] += __shfl_xor_sync(0xffffffffu, psum[i], o);
    }
    if (c4 == 0) {
        #pragma unroll
        for (int i = 0; i < 4; ++i) {
            int node = base + 4 * ng + i;
            if (node < n) pool_out[node] = psum[i];
        }
    }
}

// ---------------------------------------------------------------------------
extern "C" void kernel_launch(void* const* d_in, const int* in_sizes, int n_in,
                              void* d_out, int out_size) {
    const float* node_feat = (const float*)d_in[0];
    const int*   src       = (const int*)  d_in[1];
    const int*   dst       = (const int*)  d_in[2];
    const float* W[3] = { (const float*)d_in[4], (const float*)d_in[6], (const float*)d_in[8] };
    const float* B[3] = { (const float*)d_in[5], (const float*)d_in[7], (const float*)d_in[9] };

    const int n = in_sizes[0] / D;
    const int e = in_sizes[1];

    float* out = (float*)d_out;
    float* pool_base = out;                 // [3n]
    float* cat_base  = out + 3 * (long)n;   // [n, 192]

    int *deg_out, *deg_in, *offs, *cursor, *tsums, *toffs;
    int2 *csr;
    float *inv_out, *inv_in, *agg;
    cudaGetSymbolAddress((void**)&deg_out, g_deg_out);
    cudaGetSymbolAddress((void**)&deg_in,  g_deg_in);
    cudaGetSymbolAddress((void**)&offs,    g_offs);
    cudaGetSymbolAddress((void**)&cursor,  g_cursor);
    cudaGetSymbolAddress((void**)&csr,     g_csr);
    cudaGetSymbolAddress((void**)&inv_out, g_inv_out);
    cudaGetSymbolAddress((void**)&inv_in,  g_inv_in);
    cudaGetSymbolAddress((void**)&tsums,   g_tsums);
    cudaGetSymbolAddress((void**)&toffs,   g_toffs);
    cudaGetSymbolAddress((void**)&agg,     g_agg);

    const int T = 256;
    const int ntiles = (n + TILE - 1) / TILE;

    // --- CSR build ---
    zero_deg_kernel<<<(n + T - 1) / T, T>>>(deg_out, deg_in, n);
    deg_count_kernel<<<(e + T - 1) / T, T>>>(src, dst, deg_out, deg_in, e);
    make_inv_kernel<<<(n + T - 1) / T, T>>>(deg_out, deg_in, inv_out, inv_in, n);
    tile_sum_kernel<<<ntiles, 256>>>(deg_in, tsums, n);
    tile_offs_kernel<<<1, 1024>>>(tsums, toffs, ntiles);
    tile_scan_kernel<<<ntiles, 256>>>(deg_in, toffs, offs, cursor, n);
    place_kernel<<<(e + T - 1) / T, T>>>(src, dst, inv_out, cursor, csr, e);

    // --- 3 layers: gather -> gemm ---
    const int gather_blocks = (n * 32 + T - 1) / T;
    const int gemm_blocks   = (n + NPB - 1) / NPB;
    for (int l = 0; l < 3; ++l) {
        const float* x  = (l == 0) ? node_feat : (cat_base + (l - 1) * D);
        const int   xs2 = ((l == 0) ? D : CAT_STRIDE) / 2;   // u64 units
        gather_kernel<<<gather_blocks, T>>>(x, xs2, offs, deg_in, csr,
                                            (u64*)agg, n);
        gemm_kernel<<<gemm_blocks, T>>>(agg, inv_in, W[l], B[l],
                                        cat_base + l * D, pool_base + (long)l * n, n);
    }
}

// round 6
// speedup vs baseline: 1.9543x; 1.0313x over previous
#include <cuda_runtime.h>
#include <cuda_fp16.h>

#define MAX_N 100000
#define MAX_E 1600000
#define D 64
#define CAT_STRIDE 192  // 3*D
#define TILE 1024       // scan tile (elements)
#define MAX_TILES ((MAX_N + TILE - 1) / TILE)
#define NPB 64          // nodes per block in GEMM kernel
#define XT_STRIDE 68    // transposed smem stride (floats, mult of 4)

typedef unsigned long long u64;

// Scratch (device globals — no allocation allowed)
__device__ int     g_deg_out[MAX_N];
__device__ int     g_deg_in[MAX_N];
__device__ int     g_offs[MAX_N];
__device__ int     g_cursor[MAX_N];
__device__ int2    g_csr[MAX_E];       // (src, inv_out[src] bits)
__device__ float   g_inv_out[MAX_N];
__device__ float   g_inv_in[MAX_N];
__device__ int     g_tsums[MAX_TILES];
__device__ int     g_toffs[MAX_TILES];
__device__ float   g_agg[MAX_N * D];   // gather output (raw fp32 sums)
__device__ __half2 g_xh[MAX_N * 32];   // fp16 mirror of gather input features

// ---------------------------------------------------------------------------
// f32x2 packed helpers (sm_10x)
__device__ __forceinline__ u64 pk2(float a, float b) {
    u64 r; asm("mov.b64 %0, {%1, %2};" : "=l"(r) : "f"(a), "f"(b)); return r;
}
__device__ __forceinline__ u64 fma2(u64 a, u64 b, u64 c) {
    u64 d; asm("fma.rn.f32x2 %0, %1, %2, %3;" : "=l"(d) : "l"(a), "l"(b), "l"(c)); return d;
}
__device__ __forceinline__ float2 up2(u64 a) {
    float2 f; asm("mov.b64 {%0, %1}, %2;" : "=f"(f.x), "=f"(f.y) : "l"(a)); return f;
}

// ---------------------------------------------------------------------------
__global__ void zero_deg_kernel(int* __restrict__ a, int* __restrict__ b, int n) {
    int i = blockIdx.x * blockDim.x + threadIdx.x;
    if (i < n) { a[i] = 0; b[i] = 0; }
}

__global__ void deg_count_kernel(const int* __restrict__ src, const int* __restrict__ dst,
                                 int* __restrict__ dout, int* __restrict__ din, int e) {
    int i = blockIdx.x * blockDim.x + threadIdx.x;
    if (i < e) {
        atomicAdd(&dout[src[i]], 1);
        atomicAdd(&din[dst[i]], 1);
    }
}

__global__ void make_inv_kernel(const int* __restrict__ dout, const int* __restrict__ din,
                                float* __restrict__ iout, float* __restrict__ iin, int n) {
    int i = blockIdx.x * blockDim.x + threadIdx.x;
    if (i < n) {
        iout[i] = rsqrtf((float)max(dout[i], 1));
        iin[i]  = rsqrtf((float)max(din[i], 1));
    }
}

// Convert fp32 features -> fp16 mirror (float2 -> half2)
__global__ void to_half_kernel(const float2* __restrict__ x, __half2* __restrict__ xh, int m) {
    int i = blockIdx.x * blockDim.x + threadIdx.x;
    if (i < m) xh[i] = __float22half2_rn(x[i]);
}

// Parallel scan, stage 1: per-tile sums.
__global__ void tile_sum_kernel(const int* __restrict__ deg, int* __restrict__ tsums, int n) {
    __shared__ int wsum[8];
    int base = blockIdx.x * TILE + threadIdx.x * 4;
    int s = 0;
    #pragma unroll
    for (int j = 0; j < 4; ++j) {
        int i = base + j;
        if (i < n) s += deg[i];
    }
    #pragma unroll
    for (int o = 16; o; o >>= 1) s += __shfl_xor_sync(0xffffffffu, s, o);
    int lane = threadIdx.x & 31, w = threadIdx.x >> 5;
    if (lane == 0) wsum[w] = s;
    __syncthreads();
    if (threadIdx.x == 0) {
        int t = 0;
        #pragma unroll
        for (int j = 0; j < 8; ++j) t += wsum[j];
        tsums[blockIdx.x] = t;
    }
}

// Stage 2: exclusive scan of tile sums, one block.
__global__ void tile_offs_kernel(const int* __restrict__ tsums, int* __restrict__ toffs,
                                 int ntiles) {
    __shared__ int wsums[32];
    int tid = threadIdx.x;
    int v = (tid < ntiles) ? tsums[tid] : 0;
    int lane = tid & 31, w = tid >> 5;
    int inc = v;
    #pragma unroll
    for (int o = 1; o < 32; o <<= 1) {
        int t = __shfl_up_sync(0xffffffffu, inc, o);
        if (lane >= o) inc += t;
    }
    if (lane == 31) wsums[w] = inc;
    __syncthreads();
    if (w == 0) {
        int t = wsums[lane];
        #pragma unroll
        for (int o = 1; o < 32; o <<= 1) {
            int u = __shfl_up_sync(0xffffffffu, t, o);
            if (lane >= o) t += u;
        }
        wsums[lane] = t;
    }
    __syncthreads();
    int excl = inc - v + (w > 0 ? wsums[w - 1] : 0);
    if (tid < ntiles) toffs[tid] = excl;
}

// Stage 3: per-tile rescan with tile offset.
__global__ void tile_scan_kernel(const int* __restrict__ deg, const int* __restrict__ toffs,
                                 int* __restrict__ offs, int* __restrict__ cursor, int n) {
    __shared__ int wsums[8];
    int tid = threadIdx.x;
    int base = blockIdx.x * TILE + tid * 4;
    int d[4];
    int s = 0;
    #pragma unroll
    for (int j = 0; j < 4; ++j) {
        int i = base + j;
        d[j] = (i < n) ? deg[i] : 0;
        s += d[j];
    }
    int lane = tid & 31, w = tid >> 5;
    int inc = s;
    #pragma unroll
    for (int o = 1; o < 32; o <<= 1) {
        int t = __shfl_up_sync(0xffffffffu, inc, o);
        if (lane >= o) inc += t;
    }
    if (lane == 31) wsums[w] = inc;
    __syncthreads();
    if (w == 0 && lane < 8) {
        int t = wsums[lane];
        #pragma unroll
        for (int o = 1; o < 8; o <<= 1) {
            int u = __shfl_up_sync(0xffu, t, o);
            if (lane >= o) t += u;
        }
        wsums[lane] = t;
    }
    __syncthreads();
    int run = toffs[blockIdx.x] + (inc - s) + (w > 0 ? wsums[w - 1] : 0);
    #pragma unroll
    for (int j = 0; j < 4; ++j) {
        int i = base + j;
        if (i < n) { offs[i] = run; cursor[i] = run; }
        run += d[j];
    }
}

// Place edges into packed CSR slots.
__global__ void place_kernel(const int* __restrict__ src, const int* __restrict__ dst,
                             const float* __restrict__ inv_out,
                             int* __restrict__ cursor, int2* __restrict__ csr, int e) {
    int i = blockIdx.x * blockDim.x + threadIdx.x;
    if (i < e) {
        int s = src[i];
        int p = atomicAdd(&cursor[dst[i]], 1);
        csr[p] = make_int2(s, __float_as_int(__ldg(&inv_out[s])));
    }
}

// ---------------------------------------------------------------------------
// Gather (fp16 features, fp32 accumulation): one warp per node.
// agg[node] = sum_e xh[src_e] * scale_e  (raw, no inv_in)
__global__ void __launch_bounds__(256)
gather_kernel(const __half2* __restrict__ xh,
              const int* __restrict__ offs, const int* __restrict__ degs,
              const int2* __restrict__ csr,
              float2* __restrict__ agg, int n) {
    int node = (blockIdx.x * blockDim.x + threadIdx.x) >> 5;
    int lane = threadIdx.x & 31;
    if (node >= n) return;

    int rs  = offs[node];
    int deg = degs[node];

    float ax = 0.f, ay = 0.f, bx = 0.f, by = 0.f;
    int j = 0;
    for (; j + 8 <= deg; j += 8) {
        int2 c0 = csr[rs + j + 0];
        int2 c1 = csr[rs + j + 1];
        int2 c2 = csr[rs + j + 2];
        int2 c3 = csr[rs + j + 3];
        int2 c4 = csr[rs + j + 4];
        int2 c5 = csr[rs + j + 5];
        int2 c6 = csr[rs + j + 6];
        int2 c7 = csr[rs + j + 7];
        __half2 h0 = xh[(long)c0.x * 32 + lane];
        __half2 h1 = xh[(long)c1.x * 32 + lane];
        __half2 h2 = xh[(long)c2.x * 32 + lane];
        __half2 h3 = xh[(long)c3.x * 32 + lane];
        __half2 h4 = xh[(long)c4.x * 32 + lane];
        __half2 h5 = xh[(long)c5.x * 32 + lane];
        __half2 h6 = xh[(long)c6.x * 32 + lane];
        __half2 h7 = xh[(long)c7.x * 32 + lane];
        float2 f0 = __half22float2(h0); float s0 = __int_as_float(c0.y);
        float2 f1 = __half22float2(h1); float s1 = __int_as_float(c1.y);
        float2 f2 = __half22float2(h2); float s2 = __int_as_float(c2.y);
        float2 f3 = __half22float2(h3); float s3 = __int_as_float(c3.y);
        float2 f4 = __half22float2(h4); float s4 = __int_as_float(c4.y);
        float2 f5 = __half22float2(h5); float s5 = __int_as_float(c5.y);
        float2 f6 = __half22float2(h6); float s6 = __int_as_float(c6.y);
        float2 f7 = __half22float2(h7); float s7 = __int_as_float(c7.y);
        ax = fmaf(f0.x, s0, ax); ay = fmaf(f0.y, s0, ay);
        bx = fmaf(f1.x, s1, bx); by = fmaf(f1.y, s1, by);
        ax = fmaf(f2.x, s2, ax); ay = fmaf(f2.y, s2, ay);
        bx = fmaf(f3.x, s3, bx); by = fmaf(f3.y, s3, by);
        ax = fmaf(f4.x, s4, ax); ay = fmaf(f4.y, s4, ay);
        bx = fmaf(f5.x, s5, bx); by = fmaf(f5.y, s5, by);
        ax = fmaf(f6.x, s6, ax); ay = fmaf(f6.y, s6, ay);
        bx = fmaf(f7.x, s7, bx); by = fmaf(f7.y, s7, by);
    }
    for (; j + 4 <= deg; j += 4) {
        int2 c0 = csr[rs + j + 0];
        int2 c1 = csr[rs + j + 1];
        int2 c2 = csr[rs + j + 2];
        int2 c3 = csr[rs + j + 3];
        __half2 h0 = xh[(long)c0.x * 32 + lane];
        __half2 h1 = xh[(long)c1.x * 32 + lane];
        __half2 h2 = xh[(long)c2.x * 32 + lane];
        __half2 h3 = xh[(long)c3.x * 32 + lane];
        float2 f0 = __half22float2(h0); float s0 = __int_as_float(c0.y);
        float2 f1 = __half22float2(h1); float s1 = __int_as_float(c1.y);
        float2 f2 = __half22float2(h2); float s2 = __int_as_float(c2.y);
        float2 f3 = __half22float2(h3); float s3 = __int_as_float(c3.y);
        ax = fmaf(f0.x, s0, ax); ay = fmaf(f0.y, s0, ay);
        bx = fmaf(f1.x, s1, bx); by = fmaf(f1.y, s1, by);
        ax = fmaf(f2.x, s2, ax); ay = fmaf(f2.y, s2, ay);
        bx = fmaf(f3.x, s3, bx); by = fmaf(f3.y, s3, by);
    }
    for (; j < deg; ++j) {
        int2 c0 = csr[rs + j];
        __half2 h0 = xh[(long)c0.x * 32 + lane];
        float2 f0 = __half22float2(h0); float s0 = __int_as_float(c0.y);
        ax = fmaf(f0.x, s0, ax); ay = fmaf(f0.y, s0, ay);
    }
    agg[(long)node * 32 + lane] = make_float2(ax + bx, ay + by);
}

// ---------------------------------------------------------------------------
// GEMM: y = relu((agg * inv_in) @ W + b); block = 64 nodes, thread = 4n x 4c tile.
// Also writes fp16 mirror of y (for next layer's gather) when xh_out != null.
__global__ void __launch_bounds__(256)
gemm_kernel(const float* __restrict__ agg, const float* __restrict__ inv_in,
            const float* __restrict__ W, const float* __restrict__ b,
            float* __restrict__ cat_out, float* __restrict__ pool_out,
            __half2* __restrict__ xh_out, int n) {
    __shared__ float  xs_t[D * XT_STRIDE];   // xs_t[k * 68 + node]
    __shared__ float4 Ws4[D * 16];           // Ws4[k*16 + c4] = W[k][4c4..4c4+3]
    __shared__ float  bs[D];

    int tid  = threadIdx.x;
    int base = blockIdx.x * NPB;

    const float4* W4 = reinterpret_cast<const float4*>(W);
    #pragma unroll
    for (int r = 0; r < 4; ++r)
        Ws4[tid + 256 * r] = W4[tid + 256 * r];
    if (tid < D) bs[tid] = b[tid];

    // Stage x transposed: thread t covers node=t>>2, 16 cols (t&3)*16..+15
    {
        int node = base + (tid >> 2);
        int k16  = tid & 3;
        if (node < n) {
            float si = inv_in[node];
            const float4* af = reinterpret_cast<const float4*>(agg) + (long)node * 16;
            #pragma unroll
            for (int i = 0; i < 4; ++i) {
                float4 v = af[k16 * 4 + i];
                int k = k16 * 16 + i * 4;
                xs_t[(k + 0) * XT_STRIDE + (node - base)] = v.x * si;
                xs_t[(k + 1) * XT_STRIDE + (node - base)] = v.y * si;
                xs_t[(k + 2) * XT_STRIDE + (node - base)] = v.z * si;
                xs_t[(k + 3) * XT_STRIDE + (node - base)] = v.w * si;
            }
        }
    }
    __syncthreads();

    int c4 = tid & 15;        // col group: cols 4*c4 .. +3
    int ng = tid >> 4;        // node group: nodes base + 4*ng .. +3

    u64 acc[4][2];
    {
        u64 blo = pk2(bs[4 * c4 + 0], bs[4 * c4 + 1]);
        u64 bhi = pk2(bs[4 * c4 + 2], bs[4 * c4 + 3]);
        #pragma unroll
        for (int i = 0; i < 4; ++i) { acc[i][0] = blo; acc[i][1] = bhi; }
    }

    #pragma unroll 4
    for (int k = 0; k < D; ++k) {
        float4 w = Ws4[k * 16 + c4];
        u64 wlo = pk2(w.x, w.y);
        u64 whi = pk2(w.z, w.w);
        float4 xv = *reinterpret_cast<const float4*>(&xs_t[k * XT_STRIDE + 4 * ng]);
        u64 x0 = pk2(xv.x, xv.x);
        u64 x1 = pk2(xv.y, xv.y);
        u64 x2 = pk2(xv.z, xv.z);
        u64 x3 = pk2(xv.w, xv.w);
        acc[0][0] = fma2(x0, wlo, acc[0][0]); acc[0][1] = fma2(x0, whi, acc[0][1]);
        acc[1][0] = fma2(x1, wlo, acc[1][0]); acc[1][1] = fma2(x1, whi, acc[1][1]);
        acc[2][0] = fma2(x2, wlo, acc[2][0]); acc[2][1] = fma2(x2, whi, acc[2][1]);
        acc[3][0] = fma2(x3, wlo, acc[3][0]); acc[3][1] = fma2(x3, whi, acc[3][1]);
    }

    // Epilogue: relu, cat float4 stores, fp16 mirror, pool shfl reduce over c4
    float psum[4];
    #pragma unroll
    for (int i = 0; i < 4; ++i) {
        float2 lo = up2(acc[i][0]);
        float2 hi = up2(acc[i][1]);
        float v0 = fmaxf(lo.x, 0.f), v1 = fmaxf(lo.y, 0.f);
        float v2 = fmaxf(hi.x, 0.f), v3 = fmaxf(hi.y, 0.f);
        psum[i] = (v0 + v1) + (v2 + v3);
        int node = base + 4 * ng + i;
        if (node < n) {
            *reinterpret_cast<float4*>(cat_out + (long)node * CAT_STRIDE + 4 * c4)
                = make_float4(v0, v1, v2, v3);
            if (xh_out) {
                __half2 h01 = __floats2half2_rn(v0, v1);
                __half2 h23 = __floats2half2_rn(v2, v3);
                xh_out[(long)node * 32 + 2 * c4]     = h01;
                xh_out[(long)node * 32 + 2 * c4 + 1] = h23;
            }
        }
    }
    #pragma unroll
    for (int o = 1; o < 16; o <<= 1) {
        #pragma unroll
        for (int i = 0; i < 4; ++i)
            psum[i] += __shfl_xor_sync(0xffffffffu, psum[i], o);
    }
    if (c4 == 0) {
        #pragma unroll
        for (int i = 0; i < 4; ++i) {
            int node = base + 4 * ng + i;
            if (node < n) pool_out[node] = psum[i];
        }
    }
}

// ---------------------------------------------------------------------------
extern "C" void kernel_launch(void* const* d_in, const int* in_sizes, int n_in,
                              void* d_out, int out_size) {
    const float* node_feat = (const float*)d_in[0];
    const int*   src       = (const int*)  d_in[1];
    const int*   dst       = (const int*)  d_in[2];
    const float* W[3] = { (const float*)d_in[4], (const float*)d_in[6], (const float*)d_in[8] };
    const float* B[3] = { (const float*)d_in[5], (const float*)d_in[7], (const float*)d_in[9] };

    const int n = in_sizes[0] / D;
    const int e = in_sizes[1];

    float* out = (float*)d_out;
    float* pool_base = out;                 // [3n]
    float* cat_base  = out + 3 * (long)n;   // [n, 192]

    int *deg_out, *deg_in, *offs, *cursor, *tsums, *toffs;
    int2 *csr;
    float *inv_out, *inv_in, *agg;
    __half2* xh;
    cudaGetSymbolAddress((void**)&deg_out, g_deg_out);
    cudaGetSymbolAddress((void**)&deg_in,  g_deg_in);
    cudaGetSymbolAddress((void**)&offs,    g_offs);
    cudaGetSymbolAddress((void**)&cursor,  g_cursor);
    cudaGetSymbolAddress((void**)&csr,     g_csr);
    cudaGetSymbolAddress((void**)&inv_out, g_inv_out);
    cudaGetSymbolAddress((void**)&inv_in,  g_inv_in);
    cudaGetSymbolAddress((void**)&tsums,   g_tsums);
    cudaGetSymbolAddress((void**)&toffs,   g_toffs);
    cudaGetSymbolAddress((void**)&agg,     g_agg);
    cudaGetSymbolAddress((void**)&xh,      g_xh);

    const int T = 256;
    const int ntiles = (n + TILE - 1) / TILE;

    // --- CSR build + fp16 mirror of input features ---
    zero_deg_kernel<<<(n + T - 1) / T, T>>>(deg_out, deg_in, n);
    deg_count_kernel<<<(e + T - 1) / T, T>>>(src, dst, deg_out, deg_in, e);
    to_half_kernel<<<(n * 32 + T - 1) / T, T>>>((const float2*)node_feat, xh, n * 32);
    make_inv_kernel<<<(n + T - 1) / T, T>>>(deg_out, deg_in, inv_out, inv_in, n);
    tile_sum_kernel<<<ntiles, 256>>>(deg_in, tsums, n);
    tile_offs_kernel<<<1, 1024>>>(tsums, toffs, ntiles);
    tile_scan_kernel<<<ntiles, 256>>>(deg_in, toffs, offs, cursor, n);
    place_kernel<<<(e + T - 1) / T, T>>>(src, dst, inv_out, cursor, csr, e);

    // --- 3 layers: gather(fp16) -> gemm(fp32) ---
    const int gather_blocks = (n * 32 + T - 1) / T;
    const int gemm_blocks   = (n + NPB - 1) / NPB;
    for (int l = 0; l < 3; ++l) {
        gather_kernel<<<gather_blocks, T>>>(xh, offs, deg_in, csr, (float2*)agg, n);
        gemm_kernel<<<gemm_blocks, T>>>(agg, inv_in, W[l], B[l],
                                        cat_base + l * D, pool_base + (long)l * n,
                                        (l < 2) ? xh : (__half2*)nullptr, n);
    }
}

// round 7
// speedup vs baseline: 2.0357x; 1.0417x over previous
#include <cuda_runtime.h>
#include <cuda_fp16.h>

#define MAX_N 100000
#define MAX_E 1600000
#define D 64
#define CAT_STRIDE 192  // 3*D
#define STILE 1024
#define MAX_TILES ((MAX_N + STILE - 1) / STILE)
#define NPB 64
#define XT_STRIDE 68
#define SRCM 0x1FFFF    // 17-bit src mask (MAX_N < 131072)

typedef unsigned long long u64;

// Scratch (device globals; zero-initialized at load, re-zeroed by tail kernel)
__device__ int      g_deg_out[MAX_N];
__device__ int      g_deg_in[MAX_N];
__device__ unsigned g_status[MAX_TILES];
__device__ int2     g_rowinfo[MAX_N];    // (row start, deg)
__device__ int      g_cursor[MAX_N];
__device__ int      g_csr[MAX_E];        // src | (deg_out(src) << 17)
__device__ float    g_agg[MAX_N * D];
__device__ __half2  g_xh[MAX_N * 32];    // fp16 mirror of layer outputs

// ---------------------------------------------------------------------------
// f32x2 packed helpers (sm_10x)
__device__ __forceinline__ u64 pk2(float a, float b) {
    u64 r; asm("mov.b64 %0, {%1, %2};" : "=l"(r) : "f"(a), "f"(b)); return r;
}
__device__ __forceinline__ u64 fma2(u64 a, u64 b, u64 c) {
    u64 d; asm("fma.rn.f32x2 %0, %1, %2, %3;" : "=l"(d) : "l"(a), "l"(b), "l"(c)); return d;
}
__device__ __forceinline__ float2 up2(u64 a) {
    float2 f; asm("mov.b64 {%0, %1}, %2;" : "=f"(f.x), "=f"(f.y) : "l"(a)); return f;
}

// ---------------------------------------------------------------------------
__global__ void deg_count_kernel(const int* __restrict__ src, const int* __restrict__ dst,
                                 int* __restrict__ dout, int* __restrict__ din, int e) {
    int i = blockIdx.x * blockDim.x + threadIdx.x;
    if (i < e) {
        atomicAdd(&dout[src[i]], 1);
        atomicAdd(&din[dst[i]], 1);
    }
}

// Single-pass scan with decoupled lookback (98 tiles < 148 SMs -> all resident).
__global__ void __launch_bounds__(256)
scan_kernel(const int* __restrict__ deg, unsigned* __restrict__ status,
            int2* __restrict__ rowinfo, int* __restrict__ cursor, int n) {
    __shared__ int wsums[8];
    __shared__ int s_excl;

    int tid = threadIdx.x, lane = tid & 31, w = tid >> 5;
    int base = blockIdx.x * STILE + tid * 4;

    int d0 = 0, d1 = 0, d2 = 0, d3 = 0;
    if (base + 3 < n) {
        int4 v = *reinterpret_cast<const int4*>(deg + base);
        d0 = v.x; d1 = v.y; d2 = v.z; d3 = v.w;
    } else {
        if (base + 0 < n) d0 = deg[base + 0];
        if (base + 1 < n) d1 = deg[base + 1];
        if (base + 2 < n) d2 = deg[base + 2];
        if (base + 3 < n) d3 = deg[base + 3];
    }
    int s = d0 + d1 + d2 + d3;

    int inc = s;
    #pragma unroll
    for (int o = 1; o < 32; o <<= 1) {
        int t = __shfl_up_sync(0xffffffffu, inc, o);
        if (lane >= o) inc += t;
    }
    if (lane == 31) wsums[w] = inc;
    __syncthreads();
    if (w == 0 && lane < 8) {
        int t = wsums[lane];
        #pragma unroll
        for (int o = 1; o < 8; o <<= 1) {
            int u = __shfl_up_sync(0xffu, t, o);
            if (lane >= o) t += u;
        }
        wsums[lane] = t;
    }
    __syncthreads();
    int local_excl  = (inc - s) + (w > 0 ? wsums[w - 1] : 0);
    int block_total = wsums[7];

    // Lookback by warp 0 (flags: 0 invalid, 1 aggregate, 2 inclusive-prefix)
    if (w == 0) {
        volatile unsigned* vst = status;
        if (blockIdx.x == 0) {
            if (lane == 0) {
                vst[0] = 0x80000000u | (unsigned)block_total;
                s_excl = 0;
            }
        } else {
            if (lane == 0) vst[blockIdx.x] = 0x40000000u | (unsigned)block_total;
            int acc = 0;
            int t_hi = blockIdx.x - 1;
            bool done = false;
            while (!done) {
                int idx = t_hi - lane;
                unsigned sv;
                do {
                    sv = (idx >= 0) ? vst[idx] : 0x80000000u;
                } while (__any_sync(0xffffffffu, (sv >> 30) == 0));
                unsigned pm = __ballot_sync(0xffffffffu, (sv >> 30) == 2u);
                int val = (int)(sv & 0x3FFFFFFFu);
                int take;
                if (pm) {
                    int plane = __ffs(pm) - 1;   // closest prefix (highest idx)
                    take = (lane <= plane) ? val : 0;
                    done = true;
                } else {
                    take = (idx >= 0) ? val : 0;
                    t_hi -= 32;
                }
                #pragma unroll
                for (int o = 16; o; o >>= 1)
                    take += __shfl_xor_sync(0xffffffffu, take, o);
                acc += take;
            }
            if (lane == 0) {
                vst[blockIdx.x] = 0x80000000u | (unsigned)(acc + block_total);
                s_excl = acc;
            }
        }
    }
    __syncthreads();

    int run = s_excl + local_excl;
    if (base + 3 < n) {
        int r0 = run, r1 = r0 + d0, r2 = r1 + d1, r3 = r2 + d2;
        int4* ri = reinterpret_cast<int4*>(rowinfo + base);
        ri[0] = make_int4(r0, d0, r1, d1);
        ri[1] = make_int4(r2, d2, r3, d3);
        *reinterpret_cast<int4*>(cursor + base) = make_int4(r0, r1, r2, r3);
    } else {
        int d[4] = { d0, d1, d2, d3 };
        for (int jj = 0; jj < 4; ++jj) {
            int i = base + jj;
            if (i < n) { rowinfo[i] = make_int2(run, d[jj]); cursor[i] = run; }
            run += d[jj];
        }
    }
}

// Place edges: csr[p] = src | (deg_out(src) << 17)
__global__ void place_kernel(const int* __restrict__ src, const int* __restrict__ dst,
                             const int* __restrict__ deg_out,
                             int* __restrict__ cursor, int* __restrict__ csr, int e) {
    int i = blockIdx.x * blockDim.x + threadIdx.x;
    if (i < e) {
        int s  = src[i];
        int dg = min(__ldg(&deg_out[s]), 1023);
        int p  = atomicAdd(&cursor[dst[i]], 1);
        csr[p] = s | (dg << 17);
    }
}

// ---------------------------------------------------------------------------
// Gather: one warp per node; csr packed int (int4 = 4 edges); scale via smem LUT.
// FP16=false: x is fp32 [n,64]; FP16=true: x is __half2 mirror [n,32].
template<bool FP16>
__global__ void __launch_bounds__(256)
gather_kernel(const void* __restrict__ xin,
              const int2* __restrict__ rowinfo,
              const int* __restrict__ csr,
              float2* __restrict__ agg, int n) {
    __shared__ float lut[1024];
    for (int i = threadIdx.x; i < 1024; i += 256)
        lut[i] = rsqrtf((float)max(i, 1));
    __syncthreads();

    int node = (blockIdx.x * blockDim.x + threadIdx.x) >> 5;
    int lane = threadIdx.x & 31;
    if (node >= n) return;

    const __half2* xh = reinterpret_cast<const __half2*>(xin);
    const u64*     xf = reinterpret_cast<const u64*>(xin);

    int2 ri   = rowinfo[node];
    int  j    = ri.x;
    int  rend = ri.x + ri.y;

    float ax = 0.f, ay = 0.f, bx = 0.f, by = 0.f;

    auto edge = [&](int c, float& px, float& py) {
        int   sidx = c & SRCM;
        float sc   = lut[c >> 17];
        float2 f;
        if (FP16) f = __half22float2(xh[(long)sidx * 32 + lane]);
        else      f = up2(xf[(long)sidx * 32 + lane]);
        px = fmaf(f.x, sc, px);
        py = fmaf(f.y, sc, py);
    };

    // align to int4
    while ((j & 3) && j < rend) { edge(csr[j], ax, ay); ++j; }

    const int4* c4 = reinterpret_cast<const int4*>(csr);
    for (; j + 8 <= rend; j += 8) {
        int4 ca = c4[(j >> 2) + 0];
        int4 cb = c4[(j >> 2) + 1];
        int s0 = ca.x & SRCM, s1 = ca.y & SRCM, s2 = ca.z & SRCM, s3 = ca.w & SRCM;
        int s4 = cb.x & SRCM, s5 = cb.y & SRCM, s6 = cb.z & SRCM, s7 = cb.w & SRCM;
        float2 f0, f1, f2, f3, f4, f5, f6, f7;
        if (FP16) {
            f0 = __half22float2(xh[(long)s0 * 32 + lane]);
            f1 = __half22float2(xh[(long)s1 * 32 + lane]);
            f2 = __half22float2(xh[(long)s2 * 32 + lane]);
            f3 = __half22float2(xh[(long)s3 * 32 + lane]);
            f4 = __half22float2(xh[(long)s4 * 32 + lane]);
            f5 = __half22float2(xh[(long)s5 * 32 + lane]);
            f6 = __half22float2(xh[(long)s6 * 32 + lane]);
            f7 = __half22float2(xh[(long)s7 * 32 + lane]);
        } else {
            f0 = up2(xf[(long)s0 * 32 + lane]);
            f1 = up2(xf[(long)s1 * 32 + lane]);
            f2 = up2(xf[(long)s2 * 32 + lane]);
            f3 = up2(xf[(long)s3 * 32 + lane]);
            f4 = up2(xf[(long)s4 * 32 + lane]);
            f5 = up2(xf[(long)s5 * 32 + lane]);
            f6 = up2(xf[(long)s6 * 32 + lane]);
            f7 = up2(xf[(long)s7 * 32 + lane]);
        }
        float c0 = lut[ca.x >> 17], c1 = lut[ca.y >> 17];
        float c2 = lut[ca.z >> 17], c3 = lut[ca.w >> 17];
        float c5v = lut[cb.y >> 17], c4v = lut[cb.x >> 17];
        float c6 = lut[cb.z >> 17], c7 = lut[cb.w >> 17];
        ax = fmaf(f0.x, c0, ax);  ay = fmaf(f0.y, c0, ay);
        bx = fmaf(f1.x, c1, bx);  by = fmaf(f1.y, c1, by);
        ax = fmaf(f2.x, c2, ax);  ay = fmaf(f2.y, c2, ay);
        bx = fmaf(f3.x, c3, bx);  by = fmaf(f3.y, c3, by);
        ax = fmaf(f4.x, c4v, ax); ay = fmaf(f4.y, c4v, ay);
        bx = fmaf(f5.x, c5v, bx); by = fmaf(f5.y, c5v, by);
        ax = fmaf(f6.x, c6, ax);  ay = fmaf(f6.y, c6, ay);
        bx = fmaf(f7.x, c7, bx);  by = fmaf(f7.y, c7, by);
    }
    for (; j + 4 <= rend; j += 4) {
        int4 ca = c4[j >> 2];
        int s0 = ca.x & SRCM, s1 = ca.y & SRCM, s2 = ca.z & SRCM, s3 = ca.w & SRCM;
        float2 f0, f1, f2, f3;
        if (FP16) {
            f0 = __half22float2(xh[(long)s0 * 32 + lane]);
            f1 = __half22float2(xh[(long)s1 * 32 + lane]);
            f2 = __half22float2(xh[(long)s2 * 32 + lane]);
            f3 = __half22float2(xh[(long)s3 * 32 + lane]);
        } else {
            f0 = up2(xf[(long)s0 * 32 + lane]);
            f1 = up2(xf[(long)s1 * 32 + lane]);
            f2 = up2(xf[(long)s2 * 32 + lane]);
            f3 = up2(xf[(long)s3 * 32 + lane]);
        }
        float c0 = lut[ca.x >> 17], c1 = lut[ca.y >> 17];
        float c2 = lut[ca.z >> 17], c3 = lut[ca.w >> 17];
        ax = fmaf(f0.x, c0, ax); ay = fmaf(f0.y, c0, ay);
        bx = fmaf(f1.x, c1, bx); by = fmaf(f1.y, c1, by);
        ax = fmaf(f2.x, c2, ax); ay = fmaf(f2.y, c2, ay);
        bx = fmaf(f3.x, c3, bx); by = fmaf(f3.y, c3, by);
    }
    for (; j < rend; ++j) edge(csr[j], ax, ay);

    agg[(long)node * 32 + lane] = make_float2(ax + bx, ay + by);
}

// ---------------------------------------------------------------------------
// GEMM: y = relu((agg * rsqrt(deg_in)) @ W + b); fp16 mirror out when requested.
__global__ void __launch_bounds__(256)
gemm_kernel(const float* __restrict__ agg, const int* __restrict__ deg_in,
            const float* __restrict__ W, const float* __restrict__ b,
            float* __restrict__ cat_out, float* __restrict__ pool_out,
            __half2* __restrict__ xh_out, int n) {
    __shared__ float  xs_t[D * XT_STRIDE];
    __shared__ float4 Ws4[D * 16];
    __shared__ float  bs[D];

    int tid  = threadIdx.x;
    int base = blockIdx.x * NPB;

    const float4* W4 = reinterpret_cast<const float4*>(W);
    #pragma unroll
    for (int r = 0; r < 4; ++r)
        Ws4[tid + 256 * r] = W4[tid + 256 * r];
    if (tid < D) bs[tid] = b[tid];

    {
        int node = base + (tid >> 2);
        int k16  = tid & 3;
        if (node < n) {
            float si = rsqrtf((float)max(__ldg(&deg_in[node]), 1));
            const float4* af = reinterpret_cast<const float4*>(agg) + (long)node * 16;
            #pragma unroll
            for (int i = 0; i < 4; ++i) {
                float4 v = af[k16 * 4 + i];
                int k = k16 * 16 + i * 4;
                xs_t[(k + 0) * XT_STRIDE + (node - base)] = v.x * si;
                xs_t[(k + 1) * XT_STRIDE + (node - base)] = v.y * si;
                xs_t[(k + 2) * XT_STRIDE + (node - base)] = v.z * si;
                xs_t[(k + 3) * XT_STRIDE + (node - base)] = v.w * si;
            }
        }
    }
    __syncthreads();

    int c4 = tid & 15;
    int ng = tid >> 4;

    u64 acc[4][2];
    {
        u64 blo = pk2(bs[4 * c4 + 0], bs[4 * c4 + 1]);
        u64 bhi = pk2(bs[4 * c4 + 2], bs[4 * c4 + 3]);
        #pragma unroll
        for (int i = 0; i < 4; ++i) { acc[i][0] = blo; acc[i][1] = bhi; }
    }

    #pragma unroll 4
    for (int k = 0; k < D; ++k) {
        float4 w = Ws4[k * 16 + c4];
        u64 wlo = pk2(w.x, w.y);
        u64 whi = pk2(w.z, w.w);
        float4 xv = *reinterpret_cast<const float4*>(&xs_t[k * XT_STRIDE + 4 * ng]);
        u64 x0 = pk2(xv.x, xv.x);
        u64 x1 = pk2(xv.y, xv.y);
        u64 x2 = pk2(xv.z, xv.z);
        u64 x3 = pk2(xv.w, xv.w);
        acc[0][0] = fma2(x0, wlo, acc[0][0]); acc[0][1] = fma2(x0, whi, acc[0][1]);
        acc[1][0] = fma2(x1, wlo, acc[1][0]); acc[1][1] = fma2(x1, whi, acc[1][1]);
        acc[2][0] = fma2(x2, wlo, acc[2][0]); acc[2][1] = fma2(x2, whi, acc[2][1]);
        acc[3][0] = fma2(x3, wlo, acc[3][0]); acc[3][1] = fma2(x3, whi, acc[3][1]);
    }

    float psum[4];
    #pragma unroll
    for (int i = 0; i < 4; ++i) {
        float2 lo = up2(acc[i][0]);
        float2 hi = up2(acc[i][1]);
        float v0 = fmaxf(lo.x, 0.f), v1 = fmaxf(lo.y, 0.f);
        float v2 = fmaxf(hi.x, 0.f), v3 = fmaxf(hi.y, 0.f);
        psum[i] = (v0 + v1) + (v2 + v3);
        int node = base + 4 * ng + i;
        if (node < n) {
            *reinterpret_cast<float4*>(cat_out + (long)node * CAT_STRIDE + 4 * c4)
                = make_float4(v0, v1, v2, v3);
            if (xh_out) {
                xh_out[(long)node * 32 + 2 * c4]     = __floats2half2_rn(v0, v1);
                xh_out[(long)node * 32 + 2 * c4 + 1] = __floats2half2_rn(v2, v3);
            }
        }
    }
    #pragma unroll
    for (int o = 1; o < 16; o <<= 1) {
        #pragma unroll
        for (int i = 0; i < 4; ++i)
            psum[i] += __shfl_xor_sync(0xffffffffu, psum[i], o);
    }
    if (c4 == 0) {
        #pragma unroll
        for (int i = 0; i < 4; ++i) {
            int node = base + 4 * ng + i;
            if (node < n) pool_out[node] = psum[i];
        }
    }
}

// Tail: reset accumulators for the next graph replay.
__global__ void zero_tail_kernel(int* __restrict__ a, int* __restrict__ b,
                                 unsigned* __restrict__ st, int n, int ntiles) {
    int i = blockIdx.x * blockDim.x + threadIdx.x;
    if (i < n) { a[i] = 0; b[i] = 0; }
    if (i < ntiles) st[i] = 0u;
}

// ---------------------------------------------------------------------------
extern "C" void kernel_launch(void* const* d_in, const int* in_sizes, int n_in,
                              void* d_out, int out_size) {
    const float* node_feat = (const float*)d_in[0];
    const int*   src       = (const int*)  d_in[1];
    const int*   dst       = (const int*)  d_in[2];
    const float* W[3] = { (const float*)d_in[4], (const float*)d_in[6], (const float*)d_in[8] };
    const float* B[3] = { (const float*)d_in[5], (const float*)d_in[7], (const float*)d_in[9] };

    const int n = in_sizes[0] / D;
    const int e = in_sizes[1];

    float* out = (float*)d_out;
    float* pool_base = out;                 // [3n]
    float* cat_base  = out + 3 * (long)n;   // [n, 192]

    int *deg_out, *deg_in, *cursor, *csr;
    int2 *rowinfo;
    unsigned* status;
    float* agg;
    __half2* xh;
    cudaGetSymbolAddress((void**)&deg_out, g_deg_out);
    cudaGetSymbolAddress((void**)&deg_in,  g_deg_in);
    cudaGetSymbolAddress((void**)&status,  g_status);
    cudaGetSymbolAddress((void**)&rowinfo, g_rowinfo);
    cudaGetSymbolAddress((void**)&cursor,  g_cursor);
    cudaGetSymbolAddress((void**)&csr,     g_csr);
    cudaGetSymbolAddress((void**)&agg,     g_agg);
    cudaGetSymbolAddress((void**)&xh,      g_xh);

    const int T = 256;
    const int ntiles = (n + STILE - 1) / STILE;

    // CSR build (deg arrays and status are zero on entry: zero-init at load,
    // re-zeroed by the tail kernel on every replay)
    deg_count_kernel<<<(e + T - 1) / T, T>>>(src, dst, deg_out, deg_in, e);
    scan_kernel<<<ntiles, T>>>(deg_in, status, rowinfo, cursor, n);
    place_kernel<<<(e + T - 1) / T, T>>>(src, dst, deg_out, cursor, csr, e);

    // 3 layers: gather -> gemm
    const int gather_blocks = (n * 32 + T - 1) / T;
    const int gemm_blocks   = (n + NPB - 1) / NPB;

    gather_kernel<false><<<gather_blocks, T>>>(node_feat, rowinfo, csr, (float2*)agg, n);
    gemm_kernel<<<gemm_blocks, T>>>(agg, deg_in, W[0], B[0],
                                    cat_base + 0 * D, pool_base + 0L * n, xh, n);
    gather_kernel<true><<<gather_blocks, T>>>(xh, rowinfo, csr, (float2*)agg, n);
    gemm_kernel<<<gemm_blocks, T>>>(agg, deg_in, W[1], B[1],
                                    cat_base + 1 * D, pool_base + 1L * n, xh, n);
    gather_kernel<true><<<gather_blocks, T>>>(xh, rowinfo, csr, (float2*)agg, n);
    gemm_kernel<<<gemm_blocks, T>>>(agg, deg_in, W[2], B[2],
                                    cat_base + 2 * D, pool_base + 2L * n,
                                    (__half2*)nullptr, n);

    // reset for next replay
    zero_tail_kernel<<<(n + T - 1) / T, T>>>(deg_out, deg_in, status, n, ntiles);
}

// round 8
// speedup vs baseline: 2.1532x; 1.0577x over previous
#include <cuda_runtime.h>
#include <cuda_fp16.h>

#define MAX_N 100000
#define MAX_E 1600000
#define D 64
#define CAT_STRIDE 192  // 3*D
#define STILE 1024
#define MAX_TILES ((MAX_N + STILE - 1) / STILE)
#define NPB 64
#define XT_STRIDE 68

typedef unsigned long long u64;

// Scratch (device globals; zero-initialized at load, re-zeroed by tail kernel)
__device__ int      g_deg_out[MAX_N];
__device__ int      g_deg_in[MAX_N];
__device__ unsigned g_status[MAX_TILES];
__device__ int2     g_rowinfo[MAX_N];    // (row start, deg)
__device__ int      g_cursor[MAX_N];
__device__ int      g_csr[MAX_E];        // plain src index
__device__ float    g_agg[MAX_N * D];
__device__ __half2  g_xh[MAX_N * 32];    // fp16 mirror, PRE-SCALED by inv_out[src]

// ---------------------------------------------------------------------------
// f32x2 packed helpers (sm_10x)
__device__ __forceinline__ u64 pk2(float a, float b) {
    u64 r; asm("mov.b64 %0, {%1, %2};" : "=l"(r) : "f"(a), "f"(b)); return r;
}
__device__ __forceinline__ u64 fma2(u64 a, u64 b, u64 c) {
    u64 d; asm("fma.rn.f32x2 %0, %1, %2, %3;" : "=l"(d) : "l"(a), "l"(b), "l"(c)); return d;
}
__device__ __forceinline__ float2 up2(u64 a) {
    float2 f; asm("mov.b64 {%0, %1}, %2;" : "=f"(f.x), "=f"(f.y) : "l"(a)); return f;
}

// ---------------------------------------------------------------------------
__global__ void deg_count_kernel(const int* __restrict__ src, const int* __restrict__ dst,
                                 int* __restrict__ dout, int* __restrict__ din, int e) {
    int i = blockIdx.x * blockDim.x + threadIdx.x;
    if (i < e) {
        atomicAdd(&dout[src[i]], 1);
        atomicAdd(&din[dst[i]], 1);
    }
}

// Single-pass scan with decoupled lookback (98 tiles < 148 SMs -> all resident).
__global__ void __launch_bounds__(256)
scan_kernel(const int* __restrict__ deg, unsigned* __restrict__ status,
            int2* __restrict__ rowinfo, int* __restrict__ cursor, int n) {
    __shared__ int wsums[8];
    __shared__ int s_excl;

    int tid = threadIdx.x, lane = tid & 31, w = tid >> 5;
    int base = blockIdx.x * STILE + tid * 4;

    int d0 = 0, d1 = 0, d2 = 0, d3 = 0;
    if (base + 3 < n) {
        int4 v = *reinterpret_cast<const int4*>(deg + base);
        d0 = v.x; d1 = v.y; d2 = v.z; d3 = v.w;
    } else {
        if (base + 0 < n) d0 = deg[base + 0];
        if (base + 1 < n) d1 = deg[base + 1];
        if (base + 2 < n) d2 = deg[base + 2];
        if (base + 3 < n) d3 = deg[base + 3];
    }
    int s = d0 + d1 + d2 + d3;

    int inc = s;
    #pragma unroll
    for (int o = 1; o < 32; o <<= 1) {
        int t = __shfl_up_sync(0xffffffffu, inc, o);
        if (lane >= o) inc += t;
    }
    if (lane == 31) wsums[w] = inc;
    __syncthreads();
    if (w == 0 && lane < 8) {
        int t = wsums[lane];
        #pragma unroll
        for (int o = 1; o < 8; o <<= 1) {
            int u = __shfl_up_sync(0xffu, t, o);
            if (lane >= o) t += u;
        }
        wsums[lane] = t;
    }
    __syncthreads();
    int local_excl  = (inc - s) + (w > 0 ? wsums[w - 1] : 0);
    int block_total = wsums[7];

    if (w == 0) {
        volatile unsigned* vst = status;
        if (blockIdx.x == 0) {
            if (lane == 0) {
                vst[0] = 0x80000000u | (unsigned)block_total;
                s_excl = 0;
            }
        } else {
            if (lane == 0) vst[blockIdx.x] = 0x40000000u | (unsigned)block_total;
            int acc = 0;
            int t_hi = blockIdx.x - 1;
            bool done = false;
            while (!done) {
                int idx = t_hi - lane;
                unsigned sv;
                do {
                    sv = (idx >= 0) ? vst[idx] : 0x80000000u;
                } while (__any_sync(0xffffffffu, (sv >> 30) == 0));
                unsigned pm = __ballot_sync(0xffffffffu, (sv >> 30) == 2u);
                int val = (int)(sv & 0x3FFFFFFFu);
                int take;
                if (pm) {
                    int plane = __ffs(pm) - 1;
                    take = (lane <= plane) ? val : 0;
                    done = true;
                } else {
                    take = (idx >= 0) ? val : 0;
                    t_hi -= 32;
                }
                #pragma unroll
                for (int o = 16; o; o >>= 1)
                    take += __shfl_xor_sync(0xffffffffu, take, o);
                acc += take;
            }
            if (lane == 0) {
                vst[blockIdx.x] = 0x80000000u | (unsigned)(acc + block_total);
                s_excl = acc;
            }
        }
    }
    __syncthreads();

    int run = s_excl + local_excl;
    if (base + 3 < n) {
        int r0 = run, r1 = r0 + d0, r2 = r1 + d1, r3 = r2 + d2;
        int4* ri = reinterpret_cast<int4*>(rowinfo + base);
        ri[0] = make_int4(r0, d0, r1, d1);
        ri[1] = make_int4(r2, d2, r3, d3);
        *reinterpret_cast<int4*>(cursor + base) = make_int4(r0, r1, r2, r3);
    } else {
        int d[4] = { d0, d1, d2, d3 };
        for (int jj = 0; jj < 4; ++jj) {
            int i = base + jj;
            if (i < n) { rowinfo[i] = make_int2(run, d[jj]); cursor[i] = run; }
            run += d[jj];
        }
    }
}

// Place edges: csr[p] = src (plain index)
__global__ void place_kernel(const int* __restrict__ src, const int* __restrict__ dst,
                             int* __restrict__ cursor, int* __restrict__ csr, int e) {
    int i = blockIdx.x * blockDim.x + threadIdx.x;
    if (i < e) {
        int p = atomicAdd(&cursor[dst[i]], 1);
        csr[p] = src[i];
    }
}

// Layer-0 prescale: xh[node] = half(node_feat[node] * inv_out[node])
__global__ void prescale_kernel(const float2* __restrict__ x, const int* __restrict__ deg_out,
                                __half2* __restrict__ xh, int m) {
    int i = blockIdx.x * blockDim.x + threadIdx.x;  // one half2 per thread
    if (i < m) {
        int node = i >> 5;
        float so = rsqrtf((float)max(__ldg(&deg_out[node]), 1));
        float2 v = x[i];
        xh[i] = __floats2half2_rn(v.x * so, v.y * so);
    }
}

// ---------------------------------------------------------------------------
// Gather: one warp per node; pure row-sum of pre-scaled fp16 mirror.
__global__ void __launch_bounds__(256)
gather_kernel(const __half2* __restrict__ xh,
              const int2* __restrict__ rowinfo,
              const int* __restrict__ csr,
              float2* __restrict__ agg, int n) {
    int node = (blockIdx.x * blockDim.x + threadIdx.x) >> 5;
    int lane = threadIdx.x & 31;
    if (node >= n) return;

    int2 ri   = rowinfo[node];
    int  j    = ri.x;
    int  rend = ri.x + ri.y;

    float ax = 0.f, ay = 0.f, bx = 0.f, by = 0.f;

    // align to int4
    for (; (j & 3) && j < rend; ++j) {
        float2 f = __half22float2(xh[(long)csr[j] * 32 + lane]);
        ax += f.x; ay += f.y;
    }

    const int4* c4 = reinterpret_cast<const int4*>(csr);
    for (; j + 8 <= rend; j += 8) {
        int4 ca = c4[(j >> 2) + 0];
        int4 cb = c4[(j >> 2) + 1];
        __half2 h0 = xh[(long)ca.x * 32 + lane];
        __half2 h1 = xh[(long)ca.y * 32 + lane];
        __half2 h2 = xh[(long)ca.z * 32 + lane];
        __half2 h3 = xh[(long)ca.w * 32 + lane];
        __half2 h4 = xh[(long)cb.x * 32 + lane];
        __half2 h5 = xh[(long)cb.y * 32 + lane];
        __half2 h6 = xh[(long)cb.z * 32 + lane];
        __half2 h7 = xh[(long)cb.w * 32 + lane];
        float2 f0 = __half22float2(h0);
        float2 f1 = __half22float2(h1);
        float2 f2 = __half22float2(h2);
        float2 f3 = __half22float2(h3);
        float2 f4 = __half22float2(h4);
        float2 f5 = __half22float2(h5);
        float2 f6 = __half22float2(h6);
        float2 f7 = __half22float2(h7);
        ax += f0.x; ay += f0.y;  bx += f1.x; by += f1.y;
        ax += f2.x; ay += f2.y;  bx += f3.x; by += f3.y;
        ax += f4.x; ay += f4.y;  bx += f5.x; by += f5.y;
        ax += f6.x; ay += f6.y;  bx += f7.x; by += f7.y;
    }
    for (; j + 4 <= rend; j += 4) {
        int4 ca = c4[j >> 2];
        __half2 h0 = xh[(long)ca.x * 32 + lane];
        __half2 h1 = xh[(long)ca.y * 32 + lane];
        __half2 h2 = xh[(long)ca.z * 32 + lane];
        __half2 h3 = xh[(long)ca.w * 32 + lane];
        float2 f0 = __half22float2(h0);
        float2 f1 = __half22float2(h1);
        float2 f2 = __half22float2(h2);
        float2 f3 = __half22float2(h3);
        ax += f0.x; ay += f0.y;  bx += f1.x; by += f1.y;
        ax += f2.x; ay += f2.y;  bx += f3.x; by += f3.y;
    }
    for (; j < rend; ++j) {
        float2 f = __half22float2(xh[(long)csr[j] * 32 + lane]);
        ax += f.x; ay += f.y;
    }

    agg[(long)node * 32 + lane] = make_float2(ax + bx, ay + by);
}

// ---------------------------------------------------------------------------
// GEMM: y = relu((agg * rsqrt(deg_in)) @ W + b)
// fp16 mirror epilogue writes y * rsqrt(deg_out)  (pre-scaled for next gather)
__global__ void __launch_bounds__(256)
gemm_kernel(const float* __restrict__ agg, const int* __restrict__ deg_in,
            const int* __restrict__ deg_out,
            const float* __restrict__ W, const float* __restrict__ b,
            float* __restrict__ cat_out, float* __restrict__ pool_out,
            __half2* __restrict__ xh_out, int n) {
    __shared__ float  xs_t[D * XT_STRIDE];
    __shared__ float4 Ws4[D * 16];
    __shared__ float  bs[D];

    int tid  = threadIdx.x;
    int base = blockIdx.x * NPB;

    const float4* W4 = reinterpret_cast<const float4*>(W);
    #pragma unroll
    for (int r = 0; r < 4; ++r)
        Ws4[tid + 256 * r] = W4[tid + 256 * r];
    if (tid < D) bs[tid] = b[tid];

    {
        int node = base + (tid >> 2);
        int k16  = tid & 3;
        if (node < n) {
            float si = rsqrtf((float)max(__ldg(&deg_in[node]), 1));
            const float4* af = reinterpret_cast<const float4*>(agg) + (long)node * 16;
            #pragma unroll
            for (int i = 0; i < 4; ++i) {
                float4 v = af[k16 * 4 + i];
                int k = k16 * 16 + i * 4;
                xs_t[(k + 0) * XT_STRIDE + (node - base)] = v.x * si;
                xs_t[(k + 1) * XT_STRIDE + (node - base)] = v.y * si;
                xs_t[(k + 2) * XT_STRIDE + (node - base)] = v.z * si;
                xs_t[(k + 3) * XT_STRIDE + (node - base)] = v.w * si;
            }
        }
    }
    __syncthreads();

    int c4 = tid & 15;
    int ng = tid >> 4;

    u64 acc[4][2];
    {
        u64 blo = pk2(bs[4 * c4 + 0], bs[4 * c4 + 1]);
        u64 bhi = pk2(bs[4 * c4 + 2], bs[4 * c4 + 3]);
        #pragma unroll
        for (int i = 0; i < 4; ++i) { acc[i][0] = blo; acc[i][1] = bhi; }
    }

    #pragma unroll 4
    for (int k = 0; k < D; ++k) {
        float4 w = Ws4[k * 16 + c4];
        u64 wlo = pk2(w.x, w.y);
        u64 whi = pk2(w.z, w.w);
        float4 xv = *reinterpret_cast<const float4*>(&xs_t[k * XT_STRIDE + 4 * ng]);
        u64 x0 = pk2(xv.x, xv.x);
        u64 x1 = pk2(xv.y, xv.y);
        u64 x2 = pk2(xv.z, xv.z);
        u64 x3 = pk2(xv.w, xv.w);
        acc[0][0] = fma2(x0, wlo, acc[0][0]); acc[0][1] = fma2(x0, whi, acc[0][1]);
        acc[1][0] = fma2(x1, wlo, acc[1][0]); acc[1][1] = fma2(x1, whi, acc[1][1]);
        acc[2][0] = fma2(x2, wlo, acc[2][0]); acc[2][1] = fma2(x2, whi, acc[2][1]);
        acc[3][0] = fma2(x3, wlo, acc[3][0]); acc[3][1] = fma2(x3, whi, acc[3][1]);
    }

    float psum[4];
    #pragma unroll
    for (int i = 0; i < 4; ++i) {
        float2 lo = up2(acc[i][0]);
        float2 hi = up2(acc[i][1]);
        float v0 = fmaxf(lo.x, 0.f), v1 = fmaxf(lo.y, 0.f);
        float v2 = fmaxf(hi.x, 0.f), v3 = fmaxf(hi.y, 0.f);
        psum[i] = (v0 + v1) + (v2 + v3);
        int node = base + 4 * ng + i;
        if (node < n) {
            *reinterpret_cast<float4*>(cat_out + (long)node * CAT_STRIDE + 4 * c4)
                = make_float4(v0, v1, v2, v3);
            if (xh_out) {
                float so = rsqrtf((float)max(__ldg(&deg_out[node]), 1));
                xh_out[(long)node * 32 + 2 * c4]     = __floats2half2_rn(v0 * so, v1 * so);
                xh_out[(long)node * 32 + 2 * c4 + 1] = __floats2half2_rn(v2 * so, v3 * so);
            }
        }
    }
    #pragma unroll
    for (int o = 1; o < 16; o <<= 1) {
        #pragma unroll
        for (int i = 0; i < 4; ++i)
            psum[i] += __shfl_xor_sync(0xffffffffu, psum[i], o);
    }
    if (c4 == 0) {
        #pragma unroll
        for (int i = 0; i < 4; ++i) {
            int node = base + 4 * ng + i;
            if (node < n) pool_out[node] = psum[i];
        }
    }
}

// Tail: reset accumulators for the next graph replay.
__global__ void zero_tail_kernel(int* __restrict__ a, int* __restrict__ b,
                                 unsigned* __restrict__ st, int n, int ntiles) {
    int i = blockIdx.x * blockDim.x + threadIdx.x;
    if (i < n) { a[i] = 0; b[i] = 0; }
    if (i < ntiles) st[i] = 0u;
}

// ---------------------------------------------------------------------------
extern "C" void kernel_launch(void* const* d_in, const int* in_sizes, int n_in,
                              void* d_out, int out_size) {
    const float* node_feat = (const float*)d_in[0];
    const int*   src       = (const int*)  d_in[1];
    const int*   dst       = (const int*)  d_in[2];
    const float* W[3] = { (const float*)d_in[4], (const float*)d_in[6], (const float*)d_in[8] };
    const float* B[3] = { (const float*)d_in[5], (const float*)d_in[7], (const float*)d_in[9] };

    const int n = in_sizes[0] / D;
    const int e = in_sizes[1];

    float* out = (float*)d_out;
    float* pool_base = out;                 // [3n]
    float* cat_base  = out + 3 * (long)n;   // [n, 192]

    int *deg_out, *deg_in, *cursor, *csr;
    int2 *rowinfo;
    unsigned* status;
    float* agg;
    __half2* xh;
    cudaGetSymbolAddress((void**)&deg_out, g_deg_out);
    cudaGetSymbolAddress((void**)&deg_in,  g_deg_in);
    cudaGetSymbolAddress((void**)&status,  g_status);
    cudaGetSymbolAddress((void**)&rowinfo, g_rowinfo);
    cudaGetSymbolAddress((void**)&cursor,  g_cursor);
    cudaGetSymbolAddress((void**)&csr,     g_csr);
    cudaGetSymbolAddress((void**)&agg,     g_agg);
    cudaGetSymbolAddress((void**)&xh,      g_xh);

    const int T = 256;
    const int ntiles = (n + STILE - 1) / STILE;

    // CSR build
    deg_count_kernel<<<(e + T - 1) / T, T>>>(src, dst, deg_out, deg_in, e);
    scan_kernel<<<ntiles, T>>>(deg_in, status, rowinfo, cursor, n);
    place_kernel<<<(e + T - 1) / T, T>>>(src, dst, cursor, csr, e);
    prescale_kernel<<<(n * 32 + T - 1) / T, T>>>((const float2*)node_feat, deg_out, xh, n * 32);

    // 3 layers: gather -> gemm
    const int gather_blocks = (n * 32 + T - 1) / T;
    const int gemm_blocks   = (n + NPB - 1) / NPB;

    gather_kernel<<<gather_blocks, T>>>(xh, rowinfo, csr, (float2*)agg, n);
    gemm_kernel<<<gemm_blocks, T>>>(agg, deg_in, deg_out, W[0], B[0],
                                    cat_base + 0 * D, pool_base + 0L * n, xh, n);
    gather_kernel<<<gather_blocks, T>>>(xh, rowinfo, csr, (float2*)agg, n);
    gemm_kernel<<<gemm_blocks, T>>>(agg, deg_in, deg_out, W[1], B[1],
                                    cat_base + 1 * D, pool_base + 1L * n, xh, n);
    gather_kernel<<<gather_blocks, T>>>(xh, rowinfo, csr, (float2*)agg, n);
    gemm_kernel<<<gemm_blocks, T>>>(agg, deg_in, deg_out, W[2], B[2],
                                    cat_base + 2 * D, pool_base + 2L * n,
                                    (__half2*)nullptr, n);

    // reset for next replay
    zero_tail_kernel<<<(n + T - 1) / T, T>>>(deg_out, deg_in, status, n, ntiles);
}

// round 9
// speedup vs baseline: 2.3304x; 1.0823x over previous
#include <cuda_runtime.h>
#include <cuda_fp16.h>

#define MAX_N 100000
#define MAX_E 1600000
#define D 64
#define CAT_STRIDE 192  // 3*D
#define STILE 1024
#define MAX_TILES ((MAX_N + STILE - 1) / STILE)
#define NPB 64
#define XT_STRIDE 68

typedef unsigned long long u64;

// Scratch (device globals; zero-initialized at load, re-zeroed by tail kernel)
__device__ int      g_deg_out[MAX_N];
__device__ int      g_deg_in[MAX_N];
__device__ unsigned g_status[MAX_TILES];
__device__ int2     g_rowinfo[MAX_N];    // (row start, deg)
__device__ int      g_cursor[MAX_N];
__device__ int      g_csr[MAX_E];        // plain src index
__device__ float    g_agg[MAX_N * D];
__device__ __half2  g_xh[MAX_N * 32];    // fp16 mirror, PRE-SCALED by inv_out[src]

// ---------------------------------------------------------------------------
// f32x2 packed helpers (sm_10x)
__device__ __forceinline__ u64 pk2(float a, float b) {
    u64 r; asm("mov.b64 %0, {%1, %2};" : "=l"(r) : "f"(a), "f"(b)); return r;
}
__device__ __forceinline__ u64 fma2(u64 a, u64 b, u64 c) {
    u64 d; asm("fma.rn.f32x2 %0, %1, %2, %3;" : "=l"(d) : "l"(a), "l"(b), "l"(c)); return d;
}
__device__ __forceinline__ float2 up2(u64 a) {
    float2 f; asm("mov.b64 {%0, %1}, %2;" : "=f"(f.x), "=f"(f.y) : "l"(a)); return f;
}

// ---------------------------------------------------------------------------
// Count in-degrees only (out-degrees are counted in place_kernel's edge pass)
__global__ void deg_count_kernel(const int* __restrict__ dst,
                                 int* __restrict__ din, int e) {
    int i = blockIdx.x * blockDim.x + threadIdx.x;
    if (i < e) atomicAdd(&din[dst[i]], 1);
}

// Single-pass scan with decoupled lookback (98 tiles < 148 SMs -> all resident).
__global__ void __launch_bounds__(256)
scan_kernel(const int* __restrict__ deg, unsigned* __restrict__ status,
            int2* __restrict__ rowinfo, int* __restrict__ cursor, int n) {
    __shared__ int wsums[8];
    __shared__ int s_excl;

    int tid = threadIdx.x, lane = tid & 31, w = tid >> 5;
    int base = blockIdx.x * STILE + tid * 4;

    int d0 = 0, d1 = 0, d2 = 0, d3 = 0;
    if (base + 3 < n) {
        int4 v = *reinterpret_cast<const int4*>(deg + base);
        d0 = v.x; d1 = v.y; d2 = v.z; d3 = v.w;
    } else {
        if (base + 0 < n) d0 = deg[base + 0];
        if (base + 1 < n) d1 = deg[base + 1];
        if (base + 2 < n) d2 = deg[base + 2];
        if (base + 3 < n) d3 = deg[base + 3];
    }
    int s = d0 + d1 + d2 + d3;

    int inc = s;
    #pragma unroll
    for (int o = 1; o < 32; o <<= 1) {
        int t = __shfl_up_sync(0xffffffffu, inc, o);
        if (lane >= o) inc += t;
    }
    if (lane == 31) wsums[w] = inc;
    __syncthreads();
    if (w == 0 && lane < 8) {
        int t = wsums[lane];
        #pragma unroll
        for (int o = 1; o < 8; o <<= 1) {
            int u = __shfl_up_sync(0xffu, t, o);
            if (lane >= o) t += u;
        }
        wsums[lane] = t;
    }
    __syncthreads();
    int local_excl  = (inc - s) + (w > 0 ? wsums[w - 1] : 0);
    int block_total = wsums[7];

    if (w == 0) {
        volatile unsigned* vst = status;
        if (blockIdx.x == 0) {
            if (lane == 0) {
                vst[0] = 0x80000000u | (unsigned)block_total;
                s_excl = 0;
            }
        } else {
            if (lane == 0) vst[blockIdx.x] = 0x40000000u | (unsigned)block_total;
            int acc = 0;
            int t_hi = blockIdx.x - 1;
            bool done = false;
            while (!done) {
                int idx = t_hi - lane;
                unsigned sv;
                do {
                    sv = (idx >= 0) ? vst[idx] : 0x80000000u;
                } while (__any_sync(0xffffffffu, (sv >> 30) == 0));
                unsigned pm = __ballot_sync(0xffffffffu, (sv >> 30) == 2u);
                int val = (int)(sv & 0x3FFFFFFFu);
                int take;
                if (pm) {
                    int plane = __ffs(pm) - 1;
                    take = (lane <= plane) ? val : 0;
                    done = true;
                } else {
                    take = (idx >= 0) ? val : 0;
                    t_hi -= 32;
                }
                #pragma unroll
                for (int o = 16; o; o >>= 1)
                    take += __shfl_xor_sync(0xffffffffu, take, o);
                acc += take;
            }
            if (lane == 0) {
                vst[blockIdx.x] = 0x80000000u | (unsigned)(acc + block_total);
                s_excl = acc;
            }
        }
    }
    __syncthreads();

    int run = s_excl + local_excl;
    if (base + 3 < n) {
        int r0 = run, r1 = r0 + d0, r2 = r1 + d1, r3 = r2 + d2;
        int4* ri = reinterpret_cast<int4*>(rowinfo + base);
        ri[0] = make_int4(r0, d0, r1, d1);
        ri[1] = make_int4(r2, d2, r3, d3);
        *reinterpret_cast<int4*>(cursor + base) = make_int4(r0, r1, r2, r3);
    } else {
        int d[4] = { d0, d1, d2, d3 };
        for (int jj = 0; jj < 4; ++jj) {
            int i = base + jj;
            if (i < n) { rowinfo[i] = make_int2(run, d[jj]); cursor[i] = run; }
            run += d[jj];
        }
    }
}

// Place edges + count out-degrees in the same pass.
__global__ void place_kernel(const int* __restrict__ src, const int* __restrict__ dst,
                             int* __restrict__ cursor, int* __restrict__ csr,
                             int* __restrict__ deg_out, int e) {
    int i = blockIdx.x * blockDim.x + threadIdx.x;
    if (i < e) {
        int s = src[i];
        int p = atomicAdd(&cursor[dst[i]], 1);
        csr[p] = s;
        atomicAdd(&deg_out[s], 1);
    }
}

// Layer-0 prescale: xh[node] = half(node_feat[node] * inv_out[node])
__global__ void prescale_kernel(const float2* __restrict__ x, const int* __restrict__ deg_out,
                                __half2* __restrict__ xh, int m) {
    int i = blockIdx.x * blockDim.x + threadIdx.x;
    if (i < m) {
        int node = i >> 5;
        float so = rsqrtf((float)max(__ldg(&deg_out[node]), 1));
        float2 v = x[i];
        xh[i] = __floats2half2_rn(v.x * so, v.y * so);
    }
}

// ---------------------------------------------------------------------------
// Gather: one warp per node; 4 edges per warp-instruction group.
// Lane layout: sub = lane>>3 selects edge within group of 4; chunk = lane&7
// selects a 16B (uint4 = 8 halfs) slice of the 128B feature row.
__global__ void __launch_bounds__(256)
gather_kernel(const __half2* __restrict__ xh,
              const int2* __restrict__ rowinfo,
              const int* __restrict__ csr,
              float4* __restrict__ agg, int n) {
    int node = (blockIdx.x * blockDim.x + threadIdx.x) >> 5;
    int lane = threadIdx.x & 31;
    if (node >= n) return;

    int sub   = lane >> 3;
    int chunk = lane & 7;

    int2 ri   = rowinfo[node];
    int  j    = ri.x;
    int  rend = ri.x + ri.y;

    const uint4* __restrict__ xv = reinterpret_cast<const uint4*>(xh); // 8 uint4 per row

    float a0 = 0.f, a1 = 0.f, a2 = 0.f, a3 = 0.f;
    float a4 = 0.f, a5 = 0.f, a6 = 0.f, a7 = 0.f;

    auto accum = [&](uint4 d) {
        float2 f0 = __half22float2(*reinterpret_cast<__half2*>(&d.x));
        float2 f1 = __half22float2(*reinterpret_cast<__half2*>(&d.y));
        float2 f2 = __half22float2(*reinterpret_cast<__half2*>(&d.z));
        float2 f3 = __half22float2(*reinterpret_cast<__half2*>(&d.w));
        a0 += f0.x; a1 += f0.y;
        a2 += f1.x; a3 += f1.y;
        a4 += f2.x; a5 += f2.y;
        a6 += f3.x; a7 += f3.y;
    };

    // 8 edges per iter: two independent LDG.128 groups in flight
    for (; j + 8 <= rend; j += 8) {
        int s0 = csr[j + sub];
        int s1 = csr[j + 4 + sub];
        uint4 d0 = xv[(long)s0 * 8 + chunk];
        uint4 d1 = xv[(long)s1 * 8 + chunk];
        accum(d0);
        accum(d1);
    }
    // masked tail groups of up to 4
    for (; j < rend; j += 4) {
        int ei = j + sub;
        if (ei < rend) {
            int s = csr[ei];
            uint4 d = xv[(long)s * 8 + chunk];
            accum(d);
        }
    }

    // combine the 4 sub-groups (lanes differing in bits 3,4)
    #pragma unroll
    for (int o = 8; o <= 16; o <<= 1) {
        a0 += __shfl_xor_sync(0xffffffffu, a0, o);
        a1 += __shfl_xor_sync(0xffffffffu, a1, o);
        a2 += __shfl_xor_sync(0xffffffffu, a2, o);
        a3 += __shfl_xor_sync(0xffffffffu, a3, o);
        a4 += __shfl_xor_sync(0xffffffffu, a4, o);
        a5 += __shfl_xor_sync(0xffffffffu, a5, o);
        a6 += __shfl_xor_sync(0xffffffffu, a6, o);
        a7 += __shfl_xor_sync(0xffffffffu, a7, o);
    }
    if (sub == 0) {
        float4* ao = agg + (long)node * 16 + 2 * chunk;
        ao[0] = make_float4(a0, a1, a2, a3);
        ao[1] = make_float4(a4, a5, a6, a7);
    }
}

// ---------------------------------------------------------------------------
// GEMM: y = relu((agg * rsqrt(deg_in)) @ W + b)
// fp16 mirror epilogue writes y * rsqrt(deg_out)  (pre-scaled for next gather)
__global__ void __launch_bounds__(256)
gemm_kernel(const float* __restrict__ agg, const int* __restrict__ deg_in,
            const int* __restrict__ deg_out,
            const float* __restrict__ W, const float* __restrict__ b,
            float* __restrict__ cat_out, float* __restrict__ pool_out,
            __half2* __restrict__ xh_out, int n) {
    __shared__ float  xs_t[D * XT_STRIDE];
    __shared__ float4 Ws4[D * 16];
    __shared__ float  bs[D];

    int tid  = threadIdx.x;
    int base = blockIdx.x * NPB;

    const float4* W4 = reinterpret_cast<const float4*>(W);
    #pragma unroll
    for (int r = 0; r < 4; ++r)
        Ws4[tid + 256 * r] = W4[tid + 256 * r];
    if (tid < D) bs[tid] = b[tid];

    {
        int node = base + (tid >> 2);
        int k16  = tid & 3;
        if (node < n) {
            float si = rsqrtf((float)max(__ldg(&deg_in[node]), 1));
            const float4* af = reinterpret_cast<const float4*>(agg) + (long)node * 16;
            #pragma unroll
            for (int i = 0; i < 4; ++i) {
                float4 v = af[k16 * 4 + i];
                int k = k16 * 16 + i * 4;
                xs_t[(k + 0) * XT_STRIDE + (node - base)] = v.x * si;
                xs_t[(k + 1) * XT_STRIDE + (node - base)] = v.y * si;
                xs_t[(k + 2) * XT_STRIDE + (node - base)] = v.z * si;
                xs_t[(k + 3) * XT_STRIDE + (node - base)] = v.w * si;
            }
        }
    }
    __syncthreads();

    int c4 = tid & 15;
    int ng = tid >> 4;

    u64 acc[4][2];
    {
        u64 blo = pk2(bs[4 * c4 + 0], bs[4 * c4 + 1]);
        u64 bhi = pk2(bs[4 * c4 + 2], bs[4 * c4 + 3]);
        #pragma unroll
        for (int i = 0; i < 4; ++i) { acc[i][0] = blo; acc[i][1] = bhi; }
    }

    #pragma unroll 4
    for (int k = 0; k < D; ++k) {
        float4 w = Ws4[k * 16 + c4];
        u64 wlo = pk2(w.x, w.y);
        u64 whi = pk2(w.z, w.w);
        float4 xv = *reinterpret_cast<const float4*>(&xs_t[k * XT_STRIDE + 4 * ng]);
        u64 x0 = pk2(xv.x, xv.x);
        u64 x1 = pk2(xv.y, xv.y);
        u64 x2 = pk2(xv.z, xv.z);
        u64 x3 = pk2(xv.w, xv.w);
        acc[0][0] = fma2(x0, wlo, acc[0][0]); acc[0][1] = fma2(x0, whi, acc[0][1]);
        acc[1][0] = fma2(x1, wlo, acc[1][0]); acc[1][1] = fma2(x1, whi, acc[1][1]);
        acc[2][0] = fma2(x2, wlo, acc[2][0]); acc[2][1] = fma2(x2, whi, acc[2][1]);
        acc[3][0] = fma2(x3, wlo, acc[3][0]); acc[3][1] = fma2(x3, whi, acc[3][1]);
    }

    float psum[4];
    #pragma unroll
    for (int i = 0; i < 4; ++i) {
        float2 lo = up2(acc[i][0]);
        float2 hi = up2(acc[i][1]);
        float v0 = fmaxf(lo.x, 0.f), v1 = fmaxf(lo.y, 0.f);
        float v2 = fmaxf(hi.x, 0.f), v3 = fmaxf(hi.y, 0.f);
        psum[i] = (v0 + v1) + (v2 + v3);
        int node = base + 4 * ng + i;
        if (node < n) {
            *reinterpret_cast<float4*>(cat_out + (long)node * CAT_STRIDE + 4 * c4)
                = make_float4(v0, v1, v2, v3);
            if (xh_out) {
                float so = rsqrtf((float)max(__ldg(&deg_out[node]), 1));
                xh_out[(long)node * 32 + 2 * c4]     = __floats2half2_rn(v0 * so, v1 * so);
                xh_out[(long)node * 32 + 2 * c4 + 1] = __floats2half2_rn(v2 * so, v3 * so);
            }
        }
    }
    #pragma unroll
    for (int o = 1; o < 16; o <<= 1) {
        #pragma unroll
        for (int i = 0; i < 4; ++i)
            psum[i] += __shfl_xor_sync(0xffffffffu, psum[i], o);
    }
    if (c4 == 0) {
        #pragma unroll
        for (int i = 0; i < 4; ++i) {
            int node = base + 4 * ng + i;
            if (node < n) pool_out[node] = psum[i];
        }
    }
}

// Tail: reset accumulators for the next graph replay.
__global__ void zero_tail_kernel(int* __restrict__ a, int* __restrict__ b,
                                 unsigned* __restrict__ st, int n, int ntiles) {
    int i = blockIdx.x * blockDim.x + threadIdx.x;
    if (i < n) { a[i] = 0; b[i] = 0; }
    if (i < ntiles) st[i] = 0u;
}

// ---------------------------------------------------------------------------
extern "C" void kernel_launch(void* const* d_in, const int* in_sizes, int n_in,
                              void* d_out, int out_size) {
    const float* node_feat = (const float*)d_in[0];
    const int*   src       = (const int*)  d_in[1];
    const int*   dst       = (const int*)  d_in[2];
    const float* W[3] = { (const float*)d_in[4], (const float*)d_in[6], (const float*)d_in[8] };
    const float* B[3] = { (const float*)d_in[5], (const float*)d_in[7], (const float*)d_in[9] };

    const int n = in_sizes[0] / D;
    const int e = in_sizes[1];

    float* out = (float*)d_out;
    float* pool_base = out;                 // [3n]
    float* cat_base  = out + 3 * (long)n;   // [n, 192]

    int *deg_out, *deg_in, *cursor, *csr;
    int2 *rowinfo;
    unsigned* status;
    float* agg;
    __half2* xh;
    cudaGetSymbolAddress((void**)&deg_out, g_deg_out);
    cudaGetSymbolAddress((void**)&deg_in,  g_deg_in);
    cudaGetSymbolAddress((void**)&status,  g_status);
    cudaGetSymbolAddress((void**)&rowinfo, g_rowinfo);
    cudaGetSymbolAddress((void**)&cursor,  g_cursor);
    cudaGetSymbolAddress((void**)&csr,     g_csr);
    cudaGetSymbolAddress((void**)&agg,     g_agg);
    cudaGetSymbolAddress((void**)&xh,      g_xh);

    const int T = 256;
    const int ntiles = (n + STILE - 1) / STILE;

    // CSR build
    deg_count_kernel<<<(e + T - 1) / T, T>>>(dst, deg_in, e);
    scan_kernel<<<ntiles, T>>>(deg_in, status, rowinfo, cursor, n);
    place_kernel<<<(e + T - 1) / T, T>>>(src, dst, cursor, csr, deg_out, e);
    prescale_kernel<<<(n * 32 + T - 1) / T, T>>>((const float2*)node_feat, deg_out, xh, n * 32);

    // 3 layers: gather -> gemm
    const int gather_blocks = (n * 32 + T - 1) / T;
    const int gemm_blocks   = (n + NPB - 1) / NPB;

    gather_kernel<<<gather_blocks, T>>>(xh, rowinfo, csr, (float4*)agg, n);
    gemm_kernel<<<gemm_blocks, T>>>(agg, deg_in, deg_out, W[0], B[0],
                                    cat_base + 0 * D, pool_base + 0L * n, xh, n);
    gather_kernel<<<gather_blocks, T>>>(xh, rowinfo, csr, (float4*)agg, n);
    gemm_kernel<<<gemm_blocks, T>>>(agg, deg_in, deg_out, W[1], B[1],
                                    cat_base + 1 * D, pool_base + 1L * n, xh, n);
    gather_kernel<<<gather_blocks, T>>>(xh, rowinfo, csr, (float4*)agg, n);
    gemm_kernel<<<gemm_blocks, T>>>(agg, deg_in, deg_out, W[2], B[2],
                                    cat_base + 2 * D, pool_base + 2L * n,
                                    (__half2*)nullptr, n);

    // reset for next replay
    zero_tail_kernel<<<(n + T - 1) / T, T>>>(deg_out, deg_in, status, n, ntiles);
}